// round 1
// baseline (speedup 1.0000x reference)
#include <cuda_runtime.h>
#include <cstdint>

#define NN   100000
#define DD   128
#define EE   800000
#define NET  2
#define HH   4
#define HDM  32
#define TILE 64
#define TSTR 130            // padded SMEM row stride (floats): even (8B align) + conflict-light
#define LN_EPS 1e-5f

typedef unsigned long long ull;

// ---- scratch (device globals: allocation-free rule) ----
__device__ float g_Wh[(size_t)NET * NN * DD];   // per-etype attention outputs
__device__ float g_acc[(size_t)NN * DD];        // aggregated messages
__device__ float g_deg[NET * NN];               // degree -> inverse degree

// ---- packed f32x2 helpers ----
__device__ __forceinline__ ull pk2(float x, float y) {
    ull r; asm("mov.b64 %0, {%1, %2};" : "=l"(r) : "f"(x), "f"(y)); return r;
}
__device__ __forceinline__ ull fma2(ull a, ull b, ull c) {
    ull d; asm("fma.rn.f32x2 %0, %1, %2, %3;" : "=l"(d) : "l"(a), "l"(b), "l"(c)); return d;
}

// ---- fused transform: Wh = attn(feat @ Wt + bt) per (tile, etype) ----
// SMEM: sW[128*128] | sX[64*130] | sK | sQ | sV | sB[128] | sAt[64*16]
#define SM_W   0
#define SM_X   16384
#define SM_K   (SM_X + TILE * TSTR)
#define SM_Q   (SM_K + TILE * TSTR)
#define SM_V   (SM_Q + TILE * TSTR)
#define SM_B   (SM_V + TILE * TSTR)
#define SM_AT  (SM_B + 128)
#define SM_FLOATS (SM_AT + TILE * 16)          // 50816 floats = 203264 B

__device__ __forceinline__ void load_w(float* sW, const float* __restrict__ W, int t) {
#pragma unroll
    for (int r = 0; r < 16; r++)
        ((float4*)sW)[t + r * 256] = ((const float4*)W)[t + r * 256];
}

__device__ __forceinline__ void gemm_tile(const float* sX, const float* sW, const float* sB,
                                          int n0, int cg, ull* acc0, ull* acc1) {
#pragma unroll
    for (int i = 0; i < 8; i++) {
        float bx = sB[cg * 2 + 16 * i], by = sB[cg * 2 + 16 * i + 1];
        acc0[i] = pk2(bx, by);
        acc1[i] = acc0[i];
    }
    const float* x0 = sX + n0 * TSTR;
    const float* x1 = x0 + TSTR;
#pragma unroll 4
    for (int k = 0; k < 128; k++) {
        ull a0 = pk2(x0[k], x0[k]);
        ull a1 = pk2(x1[k], x1[k]);
        const float* wr = sW + k * 128 + cg * 2;
#pragma unroll
        for (int i = 0; i < 8; i++) {
            ull w = *(const ull*)(wr + 16 * i);
            acc0[i] = fma2(a0, w, acc0[i]);
            acc1[i] = fma2(a1, w, acc1[i]);
        }
    }
}

__device__ __forceinline__ void store_acc(float* buf, int n0, int cg, const ull* acc0, const ull* acc1) {
#pragma unroll
    for (int i = 0; i < 8; i++) {
        *(ull*)(buf + n0 * TSTR + cg * 2 + 16 * i)       = acc0[i];
        *(ull*)(buf + (n0 + 1) * TSTR + cg * 2 + 16 * i) = acc1[i];
    }
}

__global__ void __launch_bounds__(256, 1) transform_kernel(
    const float* __restrict__ feat,
    const float* __restrict__ Wt, const float* __restrict__ bt,
    const float* __restrict__ Kw, const float* __restrict__ Kb,
    const float* __restrict__ Qw, const float* __restrict__ Qb,
    const float* __restrict__ Vw, const float* __restrict__ Vb)
{
    extern __shared__ float sm[];
    float* sW = sm + SM_W;
    float* sX = sm + SM_X;
    float* sK = sm + SM_K;
    float* sQ = sm + SM_Q;
    float* sV = sm + SM_V;
    float* sB = sm + SM_B;
    float* sAt = sm + SM_AT;

    const int e    = blockIdx.y;
    const int base = blockIdx.x * TILE;
    const int t    = threadIdx.x;

    // load feat tile (guard tail tile: 1563*64 = 100032 > N)
    {
        int row = t >> 2, cq = t & 3;
        int node = base + row;
#pragma unroll
        for (int c = 0; c < 8; c++) {
            float4 v = make_float4(0.f, 0.f, 0.f, 0.f);
            if (node < NN)
                v = *(const float4*)(feat + (size_t)node * DD + cq * 32 + c * 4);
            float* d = sX + row * TSTR + cq * 32 + c * 4;
            *(float2*)d       = make_float2(v.x, v.y);
            *(float2*)(d + 2) = make_float2(v.z, v.w);
        }
    }
    load_w(sW, Wt + (size_t)e * DD * DD, t);
    if (t < 128) sB[t] = bt[e * DD + t];
    __syncthreads();

    const int n0 = (t >> 3) * 2;
    const int cg = t & 7;
    ull acc0[8], acc1[8];

    // GEMM 1: Wh0 = feat @ Wt + bt   -> overwrite sX
    gemm_tile(sX, sW, sB, n0, cg, acc0, acc1);
    __syncthreads();
    store_acc(sX, n0, cg, acc0, acc1);
    load_w(sW, Kw + (size_t)e * DD * DD, t);
    if (t < 128) sB[t] = Kb[e * DD + t];
    __syncthreads();

    // GEMM 2: K
    gemm_tile(sX, sW, sB, n0, cg, acc0, acc1);
    __syncthreads();
    store_acc(sK, n0, cg, acc0, acc1);
    load_w(sW, Qw + (size_t)e * DD * DD, t);
    if (t < 128) sB[t] = Qb[e * DD + t];
    __syncthreads();

    // GEMM 3: Q
    gemm_tile(sX, sW, sB, n0, cg, acc0, acc1);
    __syncthreads();
    store_acc(sQ, n0, cg, acc0, acc1);
    load_w(sW, Vw + (size_t)e * DD * DD, t);
    if (t < 128) sB[t] = Vb[e * DD + t];
    __syncthreads();

    // GEMM 4: V
    gemm_tile(sX, sW, sB, n0, cg, acc0, acc1);
    __syncthreads();
    store_acc(sV, n0, cg, acc0, acc1);
    __syncthreads();

    // attention phase A: scores[h][g], softmax over g  (one thread per (node, head))
    {
        int h = t >> 6;       // warp-uniform head -> conflict-light LDS
        int n = t & 63;
        float qv[HDM];
        const float* qp = sQ + n * TSTR + h * HDM;
#pragma unroll
        for (int d = 0; d < HDM; d++) qv[d] = qp[d];
        float sc[HH];
#pragma unroll
        for (int g = 0; g < HH; g++) {
            const float* kp = sK + n * TSTR + g * HDM;
            float s = 0.f;
#pragma unroll
            for (int d = 0; d < HDM; d++) s += qv[d] * kp[d];
            sc[g] = s * 0.17677669529663687f;   // 1/sqrt(32)
        }
        float m = fmaxf(fmaxf(sc[0], sc[1]), fmaxf(sc[2], sc[3]));
        float ex[HH], sum = 0.f;
#pragma unroll
        for (int g = 0; g < HH; g++) { ex[g] = __expf(sc[g] - m); sum += ex[g]; }
        float inv = 1.f / sum;
#pragma unroll
        for (int g = 0; g < HH; g++) sAt[n * 16 + h * 4 + g] = ex[g] * inv;
    }
    __syncthreads();

    // attention phase B: out[n][j] = sum_g a[n][h][g] * v[n][g*32 + d], write to g_Wh
    {
        int n = t >> 2, q = t & 3;
        int node = base + n;
        if (node < NN) {
            float* op = g_Wh + ((size_t)e * NN + node) * DD;
#pragma unroll
            for (int i = 0; i < 16; i++) {
                int j = q * 2 + 8 * i;      // even, covers 0..126
                int h2 = j >> 5, d = j & 31;
                ull accv = 0ull;            // {0.f, 0.f}
#pragma unroll
                for (int g = 0; g < HH; g++) {
                    float av = sAt[n * 16 + h2 * 4 + g];
                    ull v2 = *(const ull*)(sV + n * TSTR + g * HDM + d);
                    accv = fma2(pk2(av, av), v2, accv);
                }
                *(ull*)(op + j) = accv;
            }
        }
    }
}

// ---- zero accumulators ----
__global__ void zero_kernel() {
    int i = blockIdx.x * blockDim.x + threadIdx.x;
    ((float4*)g_acc)[i] = make_float4(0.f, 0.f, 0.f, 0.f);   // grid sized exactly NN*DD/4
    if (i < NET * NN) g_deg[i] = 0.f;
}

// ---- degree count ----
__global__ void deg_kernel(const int* __restrict__ dst) {
    int e = blockIdx.y;
    int i = blockIdx.x * blockDim.x + threadIdx.x;
    if (i < EE) atomicAdd(&g_deg[e * NN + dst[(size_t)e * EE + i]], 1.0f);
}

// ---- deg -> 1/max(deg,1) ----
__global__ void inv_kernel() {
    int i = blockIdx.x * blockDim.x + threadIdx.x;
    if (i < NET * NN) g_deg[i] = 1.0f / fmaxf(g_deg[i], 1.0f);
}

// ---- edge scatter: h[dst] += Wh[src] * inv_deg[dst]  (warp per edge, red.v4) ----
__global__ void scatter_kernel(const int* __restrict__ src, const int* __restrict__ dst, int e) {
    int wid  = (blockIdx.x * blockDim.x + threadIdx.x) >> 5;
    int lane = threadIdx.x & 31;
    if (wid >= EE) return;
    int s = __ldg(&src[(size_t)e * EE + wid]);
    int d = __ldg(&dst[(size_t)e * EE + wid]);
    float inv = g_deg[e * NN + d];
    float4 v = ((const float4*)(g_Wh + ((size_t)e * NN + s) * DD))[lane];
    float* p = g_acc + (size_t)d * DD + lane * 4;
    asm volatile("red.global.add.v4.f32 [%0], {%1, %2, %3, %4};"
                 :: "l"(p), "f"(v.x * inv), "f"(v.y * inv), "f"(v.z * inv), "f"(v.w * inv)
                 : "memory");
}

// ---- residual + LayerNorm (warp per node) ----
__global__ void finalize_kernel(const float* __restrict__ feat,
                                const float* __restrict__ ln_g, const float* __restrict__ ln_b,
                                float* __restrict__ out) {
    int w    = (blockIdx.x * blockDim.x + threadIdx.x) >> 5;
    int lane = threadIdx.x & 31;
    if (w >= NN) return;
    float4 a = ((const float4*)(g_acc + (size_t)w * DD))[lane];
    float4 f = ((const float4*)(feat + (size_t)w * DD))[lane];
    float4 h = make_float4(a.x + f.x, a.y + f.y, a.z + f.z, a.w + f.w);

    float s = h.x + h.y + h.z + h.w;
#pragma unroll
    for (int o = 16; o; o >>= 1) s += __shfl_xor_sync(0xffffffffu, s, o);
    float mu = s * (1.0f / 128.0f);

    float dx = h.x - mu, dy = h.y - mu, dz = h.z - mu, dw = h.w - mu;
    float q = dx * dx + dy * dy + dz * dz + dw * dw;
#pragma unroll
    for (int o = 16; o; o >>= 1) q += __shfl_xor_sync(0xffffffffu, q, o);
    float inv = rsqrtf(q * (1.0f / 128.0f) + LN_EPS);

    float4 gg = ((const float4*)ln_g)[lane];
    float4 bb = ((const float4*)ln_b)[lane];
    float4 o4 = make_float4(dx * inv * gg.x + bb.x, dy * inv * gg.y + bb.y,
                            dz * inv * gg.z + bb.z, dw * inv * gg.w + bb.w);
    ((float4*)out)[(size_t)w * 32 + lane] = o4;
}

extern "C" void kernel_launch(void* const* d_in, const int* in_sizes, int n_in,
                              void* d_out, int out_size) {
    const float* feat = (const float*)d_in[0];
    const int*   src  = (const int*)d_in[1];
    const int*   dst  = (const int*)d_in[2];
    const float* Wt   = (const float*)d_in[3];
    const float* bt   = (const float*)d_in[4];
    const float* Kw   = (const float*)d_in[5];
    const float* Kb   = (const float*)d_in[6];
    const float* Qw   = (const float*)d_in[7];
    const float* Qb   = (const float*)d_in[8];
    const float* Vw   = (const float*)d_in[9];
    const float* Vb   = (const float*)d_in[10];
    const float* ln_g = (const float*)d_in[11];
    const float* ln_b = (const float*)d_in[12];
    float* out = (float*)d_out;

    const size_t SMEM = SM_FLOATS * sizeof(float);   // 203264 B
    cudaFuncSetAttribute(transform_kernel, cudaFuncAttributeMaxDynamicSharedMemorySize, (int)SMEM);

    zero_kernel<<<NN * DD / 4 / 256, 256>>>();                       // 12500 blocks
    deg_kernel<<<dim3(EE / 256, NET), 256>>>(dst);                   // 3125 x 2
    inv_kernel<<<(NET * NN + 255) / 256, 256>>>();
    transform_kernel<<<dim3((NN + TILE - 1) / TILE, NET), 256, SMEM>>>(
        feat, Wt, bt, Kw, Kb, Qw, Qb, Vw, Vb);                       // 1563 x 2
    // sequential per-etype scatter keeps (Wh[e] + acc) inside L2
    scatter_kernel<<<EE / 8, 256>>>(src, dst, 0);                    // 100000 blocks
    scatter_kernel<<<EE / 8, 256>>>(src, dst, 1);
    finalize_kernel<<<(NN * 32 + 255) / 256, 256>>>(feat, ln_g, ln_b, out);
}

// round 3
// speedup vs baseline: 2.2949x; 2.2949x over previous
#include <cuda_runtime.h>
#include <cuda_bf16.h>
#include <cstdint>

#define NN   100000
#define DD   128
#define EE   800000
#define NET  2
#define TM   128
#define LN_EPS 1e-5f

#define XS 136      // bf16 row stride for X / W tiles (272B -> conflict-free ldmatrix)
#define KS 132      // fp32 row stride for K staging

// ---- smem byte offsets ----
#define OFF_XH 0
#define OFF_XL (OFF_XH + 128 * XS * 2)     // 34816
#define OFF_WH (OFF_XL + 128 * XS * 2)     // 69632
#define OFF_WL (OFF_WH + 128 * XS * 2)     // 104448
#define OFF_K  (OFF_WL + 128 * XS * 2)     // 139264
#define OFF_SC (OFF_K + 128 * KS * 4)      // 206848
#define OFF_BI (OFF_SC + 128 * 16 * 4)     // 215040
#define SMEM_BYTES (OFF_BI + 4 * 128 * 4)  // 217088

// ---- scratch (device globals: allocation-free rule) ----
__device__ float g_Wh[(size_t)NET * NN * DD];
__device__ float g_acc[(size_t)NN * DD];
__device__ float g_deg[NET * NN];

// ---- warp MMA primitives (sm_80+, safe on plain sm_103 target) ----
__device__ __forceinline__ void ldmat4(uint32_t* r, uint32_t addr) {
    asm volatile("ldmatrix.sync.aligned.m8n8.x4.shared.b16 {%0,%1,%2,%3}, [%4];"
        : "=r"(r[0]), "=r"(r[1]), "=r"(r[2]), "=r"(r[3]) : "r"(addr));
}
__device__ __forceinline__ void ldmat4t(uint32_t* r, uint32_t addr) {
    asm volatile("ldmatrix.sync.aligned.m8n8.x4.trans.shared.b16 {%0,%1,%2,%3}, [%4];"
        : "=r"(r[0]), "=r"(r[1]), "=r"(r[2]), "=r"(r[3]) : "r"(addr));
}
__device__ __forceinline__ void mma16816(float* c, const uint32_t* a, const uint32_t* b) {
    asm volatile("mma.sync.aligned.m16n8k16.row.col.f32.bf16.bf16.f32 "
        "{%0,%1,%2,%3}, {%4,%5,%6,%7}, {%8,%9}, {%0,%1,%2,%3};"
        : "+f"(c[0]), "+f"(c[1]), "+f"(c[2]), "+f"(c[3])
        : "r"(a[0]), "r"(a[1]), "r"(a[2]), "r"(a[3]), "r"(b[0]), "r"(b[1]));
}

// split two fp32 into bf16x2 hi and bf16x2 lo
__device__ __forceinline__ void split2(float a, float b, uint32_t& hi, uint32_t& lo) {
    __nv_bfloat162 h, l;
    h.x = __float2bfloat16(a); h.y = __float2bfloat16(b);
    l.x = __float2bfloat16(a - __bfloat162float(h.x));
    l.y = __float2bfloat16(b - __bfloat162float(h.y));
    hi = *(uint32_t*)&h; lo = *(uint32_t*)&l;
}

// stage a 128x128 fp32 weight (row-major [k][n]) into sWH/sWL (bf16 hi/lo, stride XS)
__device__ __forceinline__ void load_wsplit(char* smem, const float* __restrict__ W, int t) {
#pragma unroll
    for (int i = 0; i < 16; i++) {
        int u = i * 256 + t;
        int k = u >> 5, n = (u & 31) * 4;
        float4 v = *(const float4*)(W + (size_t)k * DD + n);
        uint32_t h0, l0, h1, l1;
        split2(v.x, v.y, h0, l0);
        split2(v.z, v.w, h1, l1);
        *(uint2*)(smem + OFF_WH + ((size_t)k * XS + n) * 2) = make_uint2(h0, h1);
        *(uint2*)(smem + OFF_WL + ((size_t)k * XS + n) * 2) = make_uint2(l0, l1);
    }
}

// one 128x128x128 emulated-fp32 GEMM: acc += Xh*Wh + Xh*Wl + Xl*Wh
__device__ __forceinline__ void wgemm(char* smem, float acc[16][4], int w, int lane) {
    const int r = lane & 7, sel = lane >> 3;
    const int rowoff = (sel & 1) ? 8 : 0;
    const int coloff = (sel & 2) ? 8 : 0;
    const uint32_t sb = (uint32_t)__cvta_generic_to_shared(smem);
    const int arow = 16 * w + r + rowoff;
    const uint32_t axh = sb + OFF_XH + (uint32_t)(arow * XS + coloff) * 2;
#pragma unroll
    for (int kk = 0; kk < 8; kk++) {
        uint32_t Ah[4], Al[4];
        ldmat4(Ah, axh + kk * 32);
        ldmat4(Al, axh + (OFF_XL - OFF_XH) + kk * 32);
        const int brow = kk * 16 + r + rowoff;
        const uint32_t bh = sb + OFF_WH + (uint32_t)(brow * XS + coloff) * 2;
#pragma unroll
        for (int nt16 = 0; nt16 < 8; nt16++) {
            uint32_t Bh[4], Bl[4];
            ldmat4t(Bh, bh + nt16 * 32);
            ldmat4t(Bl, bh + (OFF_WL - OFF_WH) + nt16 * 32);
            mma16816(acc[2 * nt16],     Ah, Bh);
            mma16816(acc[2 * nt16 + 1], Ah, Bh + 2);
            mma16816(acc[2 * nt16],     Ah, Bl);
            mma16816(acc[2 * nt16 + 1], Ah, Bl + 2);
            mma16816(acc[2 * nt16],     Al, Bh);
            mma16816(acc[2 * nt16 + 1], Al, Bh + 2);
        }
    }
}

__device__ __forceinline__ void zacc(float acc[16][4]) {
#pragma unroll
    for (int i = 0; i < 16; i++) { acc[i][0] = acc[i][1] = acc[i][2] = acc[i][3] = 0.f; }
}

// ================= fused transform: Wh = attn(feat @ Wt + bt) =================
__global__ void __launch_bounds__(256, 1) transform_kernel(
    const float* __restrict__ feat,
    const float* __restrict__ Wt, const float* __restrict__ bt,
    const float* __restrict__ Kw, const float* __restrict__ Kb,
    const float* __restrict__ Qw, const float* __restrict__ Qb,
    const float* __restrict__ Vw, const float* __restrict__ Vb)
{
    extern __shared__ char smem[];
    const int e    = blockIdx.y;
    const int base = blockIdx.x * TM;
    const int t    = threadIdx.x;
    const int w = t >> 5, lane = t & 31;
    const int g = lane >> 2, c = lane & 3;
    const int R0 = 16 * w + g, R1 = R0 + 8;
    float* sKf  = (float*)(smem + OFF_K);
    float* sScf = (float*)(smem + OFF_SC);
    float* sBI  = (float*)(smem + OFF_BI);

    if (t < 128) {
        sBI[t]       = bt[e * DD + t];
        sBI[128 + t] = Kb[e * DD + t];
        sBI[256 + t] = Qb[e * DD + t];
        sBI[384 + t] = Vb[e * DD + t];
    }

    // ---- feat -> X (bf16 hi/lo) ----
#pragma unroll
    for (int i = 0; i < 16; i++) {
        int u = i * 256 + t;
        int m = u >> 5, k = (u & 31) * 4;
        int node = base + m;
        float4 v = make_float4(0.f, 0.f, 0.f, 0.f);
        if (node < NN) v = *(const float4*)(feat + (size_t)node * DD + k);
        uint32_t h0, l0, h1, l1;
        split2(v.x, v.y, h0, l0);
        split2(v.z, v.w, h1, l1);
        *(uint2*)(smem + OFF_XH + ((size_t)m * XS + k) * 2) = make_uint2(h0, h1);
        *(uint2*)(smem + OFF_XL + ((size_t)m * XS + k) * 2) = make_uint2(l0, l1);
    }
    load_wsplit(smem, Wt + (size_t)e * DD * DD, t);
    __syncthreads();

    float acc[16][4];

    // ---- GEMM1: Wh0 = feat @ Wt ----
    zacc(acc);
    wgemm(smem, acc, w, lane);
    __syncthreads();                       // all warps done reading X, W

    // Wh0 + bt -> X (overwrite); Kw -> W
#pragma unroll
    for (int nt = 0; nt < 16; nt++) {
        int col = nt * 8 + 2 * c;
        float bx = sBI[col], by = sBI[col + 1];
        uint32_t h, l;
        split2(acc[nt][0] + bx, acc[nt][1] + by, h, l);
        *(uint32_t*)(smem + OFF_XH + ((size_t)R0 * XS + col) * 2) = h;
        *(uint32_t*)(smem + OFF_XL + ((size_t)R0 * XS + col) * 2) = l;
        split2(acc[nt][2] + bx, acc[nt][3] + by, h, l);
        *(uint32_t*)(smem + OFF_XH + ((size_t)R1 * XS + col) * 2) = h;
        *(uint32_t*)(smem + OFF_XL + ((size_t)R1 * XS + col) * 2) = l;
    }
    load_wsplit(smem, Kw + (size_t)e * DD * DD, t);
    __syncthreads();

    // ---- GEMM2: K = Wh0 @ Kw ----
    zacc(acc);
    wgemm(smem, acc, w, lane);
    // stage K (fp32 + bias)
#pragma unroll
    for (int nt = 0; nt < 16; nt++) {
        int col = nt * 8 + 2 * c;
        float bx = sBI[128 + col], by = sBI[128 + col + 1];
        *(float2*)(sKf + (size_t)R0 * KS + col) = make_float2(acc[nt][0] + bx, acc[nt][1] + by);
        *(float2*)(sKf + (size_t)R1 * KS + col) = make_float2(acc[nt][2] + bx, acc[nt][3] + by);
    }
    __syncthreads();                       // all done with Kw + K staged
    load_wsplit(smem, Qw + (size_t)e * DD * DD, t);
    __syncthreads();

    // ---- GEMM3: Q ----
    zacc(acc);
    wgemm(smem, acc, w, lane);
#pragma unroll
    for (int nt = 0; nt < 16; nt++) {      // + Qb
        int col = nt * 8 + 2 * c;
        float bx = sBI[256 + col], by = sBI[256 + col + 1];
        acc[nt][0] += bx; acc[nt][1] += by;
        acc[nt][2] += bx; acc[nt][3] += by;
    }

    // ---- scores[n][h][g'] = q.k / sqrt(32), via fragment-local dot + 4-lane shfl ----
    const float scale = 0.17677669529663687f;
#pragma unroll
    for (int gp = 0; gp < 4; gp++) {
        float2 kv0[4], kv1[4];
#pragma unroll
        for (int j = 0; j < 4; j++) {
            kv0[j] = *(float2*)(sKf + (size_t)R0 * KS + gp * 32 + j * 8 + 2 * c);
            kv1[j] = *(float2*)(sKf + (size_t)R1 * KS + gp * 32 + j * 8 + 2 * c);
        }
#pragma unroll
        for (int h = 0; h < 4; h++) {
            float p0 = 0.f, p1 = 0.f;
#pragma unroll
            for (int j = 0; j < 4; j++) {
                p0 += acc[4 * h + j][0] * kv0[j].x + acc[4 * h + j][1] * kv0[j].y;
                p1 += acc[4 * h + j][2] * kv1[j].x + acc[4 * h + j][3] * kv1[j].y;
            }
            p0 += __shfl_xor_sync(0xffffffffu, p0, 1);
            p0 += __shfl_xor_sync(0xffffffffu, p0, 2);
            p1 += __shfl_xor_sync(0xffffffffu, p1, 1);
            p1 += __shfl_xor_sync(0xffffffffu, p1, 2);
            if (c == 0) {
                sScf[R0 * 16 + h * 4 + gp] = p0 * scale;
                sScf[R1 * 16 + h * 4 + gp] = p1 * scale;
            }
        }
    }
    __syncthreads();

    // ---- softmax over g' (512 (row,head) pairs / 256 threads) + load Vw ----
#pragma unroll
    for (int i = 0; i < 2; i++) {
        int p = t * 2 + i;
        int row = p >> 2, h = p & 3;
        float4 s = *(float4*)(sScf + row * 16 + h * 4);
        float m = fmaxf(fmaxf(s.x, s.y), fmaxf(s.z, s.w));
        float e0 = __expf(s.x - m), e1 = __expf(s.y - m), e2 = __expf(s.z - m), e3 = __expf(s.w - m);
        float inv = 1.f / (e0 + e1 + e2 + e3);
        *(float4*)(sScf + row * 16 + h * 4) = make_float4(e0 * inv, e1 * inv, e2 * inv, e3 * inv);
    }
    load_wsplit(smem, Vw + (size_t)e * DD * DD, t);
    __syncthreads();

    // ---- GEMM4: V ----
    zacc(acc);
    wgemm(smem, acc, w, lane);
#pragma unroll
    for (int nt = 0; nt < 16; nt++) {      // + Vb
        int col = nt * 8 + 2 * c;
        float bx = sBI[384 + col], by = sBI[384 + col + 1];
        acc[nt][0] += bx; acc[nt][1] += by;
        acc[nt][2] += bx; acc[nt][3] += by;
    }

    // ---- combine: out[R][nt*8+2c+i] = sum_g a[R][(nt>>2)*4+g] * v[R][g*32+(nt&3)*8+2c+i]
    // v column needed lives in the SAME lane, n-tile g*4+(nt&3) -> zero cross-lane traffic.
    float aw0[16], aw1[16];
#pragma unroll
    for (int i = 0; i < 4; i++) {
        *(float4*)(aw0 + 4 * i) = *(float4*)(sScf + R0 * 16 + 4 * i);
        *(float4*)(aw1 + 4 * i) = *(float4*)(sScf + R1 * 16 + 4 * i);
    }
    const int n0 = base + R0, n1 = base + R1;
#pragma unroll
    for (int nt = 0; nt < 16; nt++) {
        int h = nt >> 2, j3 = nt & 3;
        int col = nt * 8 + 2 * c;
        float o00 = 0.f, o01 = 0.f, o10 = 0.f, o11 = 0.f;
#pragma unroll
        for (int gi = 0; gi < 4; gi++) {
            float a0 = aw0[h * 4 + gi], a1 = aw1[h * 4 + gi];
            o00 += a0 * acc[gi * 4 + j3][0];
            o01 += a0 * acc[gi * 4 + j3][1];
            o10 += a1 * acc[gi * 4 + j3][2];
            o11 += a1 * acc[gi * 4 + j3][3];
        }
        if (n0 < NN) *(float2*)(g_Wh + ((size_t)e * NN + n0) * DD + col) = make_float2(o00, o01);
        if (n1 < NN) *(float2*)(g_Wh + ((size_t)e * NN + n1) * DD + col) = make_float2(o10, o11);
    }
}

// ---- zero accumulators ----
__global__ void zero_kernel() {
    int i = blockIdx.x * blockDim.x + threadIdx.x;
    ((float4*)g_acc)[i] = make_float4(0.f, 0.f, 0.f, 0.f);
    if (i < NET * NN) g_deg[i] = 0.f;
}

// ---- degree count ----
__global__ void deg_kernel(const int* __restrict__ dst) {
    int e = blockIdx.y;
    int i = blockIdx.x * blockDim.x + threadIdx.x;
    if (i < EE) atomicAdd(&g_deg[e * NN + dst[(size_t)e * EE + i]], 1.0f);
}

// ---- deg -> 1/max(deg,1) ----
__global__ void inv_kernel() {
    int i = blockIdx.x * blockDim.x + threadIdx.x;
    if (i < NET * NN) g_deg[i] = 1.0f / fmaxf(g_deg[i], 1.0f);
}

// ---- edge scatter: h[dst] += Wh[src] * inv_deg[dst] (warp per edge, red.v4) ----
__global__ void scatter_kernel(const int* __restrict__ src, const int* __restrict__ dst, int e) {
    int wid  = (blockIdx.x * blockDim.x + threadIdx.x) >> 5;
    int lane = threadIdx.x & 31;
    if (wid >= EE) return;
    int s = __ldg(&src[(size_t)e * EE + wid]);
    int d = __ldg(&dst[(size_t)e * EE + wid]);
    float inv = g_deg[e * NN + d];
    float4 v = ((const float4*)(g_Wh + ((size_t)e * NN + s) * DD))[lane];
    float* p = g_acc + (size_t)d * DD + lane * 4;
    asm volatile("red.global.add.v4.f32 [%0], {%1, %2, %3, %4};"
                 :: "l"(p), "f"(v.x * inv), "f"(v.y * inv), "f"(v.z * inv), "f"(v.w * inv)
                 : "memory");
}

// ---- residual + LayerNorm (warp per node) ----
__global__ void finalize_kernel(const float* __restrict__ feat,
                                const float* __restrict__ ln_g, const float* __restrict__ ln_b,
                                float* __restrict__ out) {
    int w    = (blockIdx.x * blockDim.x + threadIdx.x) >> 5;
    int lane = threadIdx.x & 31;
    if (w >= NN) return;
    float4 a = ((const float4*)(g_acc + (size_t)w * DD))[lane];
    float4 f = ((const float4*)(feat + (size_t)w * DD))[lane];
    float4 h = make_float4(a.x + f.x, a.y + f.y, a.z + f.z, a.w + f.w);

    float s = h.x + h.y + h.z + h.w;
#pragma unroll
    for (int o = 16; o; o >>= 1) s += __shfl_xor_sync(0xffffffffu, s, o);
    float mu = s * (1.0f / 128.0f);

    float dx = h.x - mu, dy = h.y - mu, dz = h.z - mu, dw = h.w - mu;
    float q = dx * dx + dy * dy + dz * dz + dw * dw;
#pragma unroll
    for (int o = 16; o; o >>= 1) q += __shfl_xor_sync(0xffffffffu, q, o);
    float inv = rsqrtf(q * (1.0f / 128.0f) + LN_EPS);

    float4 gg = ((const float4*)ln_g)[lane];
    float4 bb = ((const float4*)ln_b)[lane];
    float4 o4 = make_float4(dx * inv * gg.x + bb.x, dy * inv * gg.y + bb.y,
                            dz * inv * gg.z + bb.z, dw * inv * gg.w + bb.w);
    ((float4*)out)[(size_t)w * 32 + lane] = o4;
}

extern "C" void kernel_launch(void* const* d_in, const int* in_sizes, int n_in,
                              void* d_out, int out_size) {
    const float* feat = (const float*)d_in[0];
    const int*   src  = (const int*)d_in[1];
    const int*   dst  = (const int*)d_in[2];
    const float* Wt   = (const float*)d_in[3];
    const float* bt   = (const float*)d_in[4];
    const float* Kw   = (const float*)d_in[5];
    const float* Kb   = (const float*)d_in[6];
    const float* Qw   = (const float*)d_in[7];
    const float* Qb   = (const float*)d_in[8];
    const float* Vw   = (const float*)d_in[9];
    const float* Vb   = (const float*)d_in[10];
    const float* ln_g = (const float*)d_in[11];
    const float* ln_b = (const float*)d_in[12];
    float* out = (float*)d_out;

    cudaFuncSetAttribute(transform_kernel, cudaFuncAttributeMaxDynamicSharedMemorySize, SMEM_BYTES);

    zero_kernel<<<NN * DD / 4 / 256, 256>>>();
    deg_kernel<<<dim3(EE / 256, NET), 256>>>(dst);
    inv_kernel<<<(NET * NN + 255) / 256, 256>>>();
    transform_kernel<<<dim3((NN + TM - 1) / TM, NET), 256, SMEM_BYTES>>>(
        feat, Wt, bt, Kw, Kb, Qw, Qb, Vw, Vb);
    // sequential per-etype scatter keeps (Wh[e] + acc) inside L2
    scatter_kernel<<<EE / 8, 256>>>(src, dst, 0);
    scatter_kernel<<<EE / 8, 256>>>(src, dst, 1);
    finalize_kernel<<<(NN * 32 + 255) / 256, 256>>>(feat, ln_g, ln_b, out);
}

// round 4
// speedup vs baseline: 3.4694x; 1.5118x over previous
#include <cuda_runtime.h>
#include <cuda_bf16.h>
#include <cstdint>

#define NN   100000
#define DD   128
#define EE   800000
#define NET  2
#define TM   128
#define LN_EPS 1e-5f

#define XS 136      // bf16 row stride (272B -> conflict-free ldmatrix)
#define KS 132      // fp32 row stride for K staging
#define LODELTA 34816   // hi-plane -> lo-plane smem delta (128*136*2)

// ---- smem byte offsets ----
#define OFF_XH 0
#define OFF_W0 69632                       // X (hi+lo) = 2*34816
#define OFF_W1 139264
#define OFF_SC 208896
#define OFF_BI 217088
#define SMEM_BYTES 219136

// ---- scratch (device globals) ----
__device__ float g_Wh[(size_t)NET * NN * DD];
__device__ __nv_bfloat16 g_Wsplit[NET * 4 * 2 * DD * DD];   // [e][mat][hi/lo][128][128]
__device__ int g_cnt[NET * NN];
__device__ int g_off[NET * NN + 1];
__device__ int g_cur[NET * NN];
__device__ int g_bsum[256];
__device__ int g_sorted[NET * EE];

// ---- warp MMA primitives ----
__device__ __forceinline__ void ldmat4(uint32_t* r, uint32_t addr) {
    asm volatile("ldmatrix.sync.aligned.m8n8.x4.shared.b16 {%0,%1,%2,%3}, [%4];"
        : "=r"(r[0]), "=r"(r[1]), "=r"(r[2]), "=r"(r[3]) : "r"(addr));
}
__device__ __forceinline__ void ldmat4t(uint32_t* r, uint32_t addr) {
    asm volatile("ldmatrix.sync.aligned.m8n8.x4.trans.shared.b16 {%0,%1,%2,%3}, [%4];"
        : "=r"(r[0]), "=r"(r[1]), "=r"(r[2]), "=r"(r[3]) : "r"(addr));
}
__device__ __forceinline__ void mma16816(float* c, const uint32_t* a, const uint32_t* b) {
    asm volatile("mma.sync.aligned.m16n8k16.row.col.f32.bf16.bf16.f32 "
        "{%0,%1,%2,%3}, {%4,%5,%6,%7}, {%8,%9}, {%0,%1,%2,%3};"
        : "+f"(c[0]), "+f"(c[1]), "+f"(c[2]), "+f"(c[3])
        : "r"(a[0]), "r"(a[1]), "r"(a[2]), "r"(a[3]), "r"(b[0]), "r"(b[1]));
}
#define CP_COMMIT() asm volatile("cp.async.commit_group;" ::: "memory")
#define CP_WAIT(n)  asm volatile("cp.async.wait_group %0;" :: "n"(n) : "memory")

__device__ __forceinline__ void split2(float a, float b, uint32_t& hi, uint32_t& lo) {
    __nv_bfloat162 h, l;
    h.x = __float2bfloat16(a); h.y = __float2bfloat16(b);
    l.x = __float2bfloat16(a - __bfloat162float(h.x));
    l.y = __float2bfloat16(b - __bfloat162float(h.y));
    hi = *(uint32_t*)&h; lo = *(uint32_t*)&l;
}

// cp.async one weight stage (hi+lo planes, 32KB each) into XS-strided smem
__device__ __forceinline__ void cpw(uint32_t sb, int offW, const __nv_bfloat16* __restrict__ gsrc, int t) {
#pragma unroll
    for (int i = 0; i < 8; i++) {
        int u = i * 256 + t;             // 0..2047
        int k = u >> 4, n16 = u & 15;
        uint32_t dh = sb + offW + k * (XS * 2) + n16 * 16;
        const char* gh = (const char*)gsrc + k * 256 + n16 * 16;
        asm volatile("cp.async.cg.shared.global [%0], [%1], 16;" :: "r"(dh), "l"(gh));
        asm volatile("cp.async.cg.shared.global [%0], [%1], 16;" :: "r"(dh + LODELTA), "l"(gh + 32768));
    }
}

// emulated-fp32 GEMM: FULL -> Xh*Wh + Xh*Wl + Xl*Wh; else Xh*Wh only
template<bool FULL>
__device__ __forceinline__ void wgemm(char* smem, float acc[16][4], int offW, int w, int lane) {
    const int r = lane & 7, sel = lane >> 3;
    const int rowoff = (sel & 1) ? 8 : 0;
    const int coloff = (sel & 2) ? 8 : 0;
    const uint32_t sb = (uint32_t)__cvta_generic_to_shared(smem);
    const int arow = 16 * w + r + rowoff;
    const uint32_t axh = sb + OFF_XH + (uint32_t)(arow * XS + coloff) * 2;
#pragma unroll
    for (int kk = 0; kk < 8; kk++) {
        uint32_t Ah[4], Al[4];
        ldmat4(Ah, axh + kk * 32);
        if (FULL) ldmat4(Al, axh + LODELTA + kk * 32);
        const int brow = kk * 16 + r + rowoff;
        const uint32_t bh = sb + offW + (uint32_t)(brow * XS + coloff) * 2;
#pragma unroll
        for (int nt16 = 0; nt16 < 8; nt16++) {
            uint32_t Bh[4], Bl[4];
            ldmat4t(Bh, bh + nt16 * 32);
            if (FULL) ldmat4t(Bl, bh + LODELTA + nt16 * 32);
            mma16816(acc[2 * nt16],     Ah, Bh);
            mma16816(acc[2 * nt16 + 1], Ah, Bh + 2);
            if (FULL) {
                mma16816(acc[2 * nt16],     Ah, Bl);
                mma16816(acc[2 * nt16 + 1], Ah, Bl + 2);
                mma16816(acc[2 * nt16],     Al, Bh);
                mma16816(acc[2 * nt16 + 1], Al, Bh + 2);
            }
        }
    }
}

__device__ __forceinline__ void zacc(float acc[16][4]) {
#pragma unroll
    for (int i = 0; i < 16; i++) { acc[i][0] = acc[i][1] = acc[i][2] = acc[i][3] = 0.f; }
}

// ---- pre-split weights: fp32 -> bf16 hi/lo planes ----
__global__ void wsplit_kernel(const float* __restrict__ Wt, const float* __restrict__ Kw,
                              const float* __restrict__ Qw, const float* __restrict__ Vw) {
    int i = blockIdx.x * 256 + threadIdx.x;   // 0..65535
    int mat = i >> 14, j = i & 16383;
    int e = blockIdx.y;
    const float* srcs[4] = {Wt, Kw, Qw, Vw};
    float v = srcs[mat][(size_t)e * 16384 + j];
    __nv_bfloat16 h = __float2bfloat16(v);
    __nv_bfloat16 l = __float2bfloat16(v - __bfloat162float(h));
    size_t b = ((size_t)(e * 4 + mat) * 2) * 16384;
    g_Wsplit[b + j] = h;
    g_Wsplit[b + 16384 + j] = l;
}

// ================= fused transform =================
__global__ void __launch_bounds__(256, 1) transform_kernel(
    const float* __restrict__ feat,
    const float* __restrict__ bt, const float* __restrict__ Kb,
    const float* __restrict__ Qb, const float* __restrict__ Vb)
{
    extern __shared__ char smem[];
    const uint32_t sb = (uint32_t)__cvta_generic_to_shared(smem);
    const int e    = blockIdx.y;
    const int base = blockIdx.x * TM;
    const int t    = threadIdx.x;
    const int w = t >> 5, lane = t & 31;
    const int g = lane >> 2, c = lane & 3;
    const int R0 = 16 * w + g, R1 = R0 + 8;
    float* sKf  = (float*)(smem + OFF_W1);
    float* sScf = (float*)(smem + OFF_SC);
    float* sBI  = (float*)(smem + OFF_BI);
    const __nv_bfloat16* Wb = g_Wsplit + (size_t)e * 4 * 2 * 16384;

    cpw(sb, OFF_W0, Wb,             t); CP_COMMIT();   // Wt
    cpw(sb, OFF_W1, Wb + 2 * 16384, t); CP_COMMIT();   // Kw

    if (t < 128) {
        sBI[t]       = bt[e * DD + t];
        sBI[128 + t] = Kb[e * DD + t];
        sBI[256 + t] = Qb[e * DD + t];
        sBI[384 + t] = Vb[e * DD + t];
    }

    // feat -> X (bf16 hi/lo)   (overlaps with cp.async weight loads)
#pragma unroll
    for (int i = 0; i < 16; i++) {
        int u = i * 256 + t;
        int m = u >> 5, k = (u & 31) * 4;
        int node = base + m;
        float4 v = make_float4(0.f, 0.f, 0.f, 0.f);
        if (node < NN) v = *(const float4*)(feat + (size_t)node * DD + k);
        uint32_t h0, l0, h1, l1;
        split2(v.x, v.y, h0, l0);
        split2(v.z, v.w, h1, l1);
        *(uint2*)(smem + OFF_XH + ((size_t)m * XS + k) * 2) = make_uint2(h0, h1);
        *(uint2*)(smem + OFF_XH + LODELTA + ((size_t)m * XS + k) * 2) = make_uint2(l0, l1);
    }
    CP_WAIT(1);
    __syncthreads();

    float acc[16][4];

    // ---- GEMM1: Wh0 = feat @ Wt (full) ----
    zacc(acc);
    wgemm<true>(smem, acc, OFF_W0, w, lane);
    __syncthreads();

    // Wh0 + bt -> X
#pragma unroll
    for (int nt = 0; nt < 16; nt++) {
        int col = nt * 8 + 2 * c;
        float bx = sBI[col], by = sBI[col + 1];
        uint32_t h, l;
        split2(acc[nt][0] + bx, acc[nt][1] + by, h, l);
        *(uint32_t*)(smem + OFF_XH + ((size_t)R0 * XS + col) * 2) = h;
        *(uint32_t*)(smem + OFF_XH + LODELTA + ((size_t)R0 * XS + col) * 2) = l;
        split2(acc[nt][2] + bx, acc[nt][3] + by, h, l);
        *(uint32_t*)(smem + OFF_XH + ((size_t)R1 * XS + col) * 2) = h;
        *(uint32_t*)(smem + OFF_XH + LODELTA + ((size_t)R1 * XS + col) * 2) = l;
    }
    cpw(sb, OFF_W0, Wb + 4 * 16384, t); CP_COMMIT();   // Qw
    CP_WAIT(1);                                        // Kw ready
    __syncthreads();

    // ---- GEMM2: K (hi-only) ----
    zacc(acc);
    wgemm<false>(smem, acc, OFF_W1, w, lane);
    __syncthreads();                                   // Kw reads done

    // stage K (+Kb) into B1
#pragma unroll
    for (int nt = 0; nt < 16; nt++) {
        int col = nt * 8 + 2 * c;
        float bx = sBI[128 + col], by = sBI[128 + col + 1];
        *(float2*)(sKf + (size_t)R0 * KS + col) = make_float2(acc[nt][0] + bx, acc[nt][1] + by);
        *(float2*)(sKf + (size_t)R1 * KS + col) = make_float2(acc[nt][2] + bx, acc[nt][3] + by);
    }
    CP_WAIT(0);                                        // Qw ready
    __syncthreads();

    // ---- GEMM3: Q (hi-only) ----
    zacc(acc);
    wgemm<false>(smem, acc, OFF_W0, w, lane);
#pragma unroll
    for (int nt = 0; nt < 16; nt++) {
        int col = nt * 8 + 2 * c;
        float bx = sBI[256 + col], by = sBI[256 + col + 1];
        acc[nt][0] += bx; acc[nt][1] += by;
        acc[nt][2] += bx; acc[nt][3] += by;
    }

    // ---- scores ----
    const float scale = 0.17677669529663687f;
#pragma unroll
    for (int gp = 0; gp < 4; gp++) {
        float2 kv0[4], kv1[4];
#pragma unroll
        for (int j = 0; j < 4; j++) {
            kv0[j] = *(float2*)(sKf + (size_t)R0 * KS + gp * 32 + j * 8 + 2 * c);
            kv1[j] = *(float2*)(sKf + (size_t)R1 * KS + gp * 32 + j * 8 + 2 * c);
        }
#pragma unroll
        for (int h = 0; h < 4; h++) {
            float p0 = 0.f, p1 = 0.f;
#pragma unroll
            for (int j = 0; j < 4; j++) {
                p0 += acc[4 * h + j][0] * kv0[j].x + acc[4 * h + j][1] * kv0[j].y;
                p1 += acc[4 * h + j][2] * kv1[j].x + acc[4 * h + j][3] * kv1[j].y;
            }
            p0 += __shfl_xor_sync(0xffffffffu, p0, 1);
            p0 += __shfl_xor_sync(0xffffffffu, p0, 2);
            p1 += __shfl_xor_sync(0xffffffffu, p1, 1);
            p1 += __shfl_xor_sync(0xffffffffu, p1, 2);
            if (c == 0) {
                sScf[R0 * 16 + h * 4 + gp] = p0 * scale;
                sScf[R1 * 16 + h * 4 + gp] = p1 * scale;
            }
        }
    }
    __syncthreads();                                   // scores visible, K reads done

    cpw(sb, OFF_W1, Wb + 6 * 16384, t); CP_COMMIT();   // Vw (overlaps softmax)

    // ---- softmax ----
#pragma unroll
    for (int i = 0; i < 2; i++) {
        int p = t * 2 + i;
        int row = p >> 2, h = p & 3;
        float4 s = *(float4*)(sScf + row * 16 + h * 4);
        float m = fmaxf(fmaxf(s.x, s.y), fmaxf(s.z, s.w));
        float e0 = __expf(s.x - m), e1 = __expf(s.y - m), e2 = __expf(s.z - m), e3 = __expf(s.w - m);
        float inv = 1.f / (e0 + e1 + e2 + e3);
        *(float4*)(sScf + row * 16 + h * 4) = make_float4(e0 * inv, e1 * inv, e2 * inv, e3 * inv);
    }
    CP_WAIT(0);
    __syncthreads();

    // ---- GEMM4: V (full) ----
    zacc(acc);
    wgemm<true>(smem, acc, OFF_W1, w, lane);
#pragma unroll
    for (int nt = 0; nt < 16; nt++) {
        int col = nt * 8 + 2 * c;
        float bx = sBI[384 + col], by = sBI[384 + col + 1];
        acc[nt][0] += bx; acc[nt][1] += by;
        acc[nt][2] += bx; acc[nt][3] += by;
    }

    // ---- combine -> g_Wh ----
    float aw0[16], aw1[16];
#pragma unroll
    for (int i = 0; i < 4; i++) {
        *(float4*)(aw0 + 4 * i) = *(float4*)(sScf + R0 * 16 + 4 * i);
        *(float4*)(aw1 + 4 * i) = *(float4*)(sScf + R1 * 16 + 4 * i);
    }
    const int n0 = base + R0, n1 = base + R1;
#pragma unroll
    for (int nt = 0; nt < 16; nt++) {
        int h = nt >> 2, j3 = nt & 3;
        int col = nt * 8 + 2 * c;
        float o00 = 0.f, o01 = 0.f, o10 = 0.f, o11 = 0.f;
#pragma unroll
        for (int gi = 0; gi < 4; gi++) {
            float a0 = aw0[h * 4 + gi], a1 = aw1[h * 4 + gi];
            o00 += a0 * acc[gi * 4 + j3][0];
            o01 += a0 * acc[gi * 4 + j3][1];
            o10 += a1 * acc[gi * 4 + j3][2];
            o11 += a1 * acc[gi * 4 + j3][3];
        }
        if (n0 < NN) *(float2*)(g_Wh + ((size_t)e * NN + n0) * DD + col) = make_float2(o00, o01);
        if (n1 < NN) *(float2*)(g_Wh + ((size_t)e * NN + n1) * DD + col) = make_float2(o10, o11);
    }
}

// ================= CSR build =================
__global__ void cnt_zero_kernel() {
    int i = blockIdx.x * 1024 + threadIdx.x;
    if (i < NET * NN) g_cnt[i] = 0;
}
__global__ void cnt_kernel(const int* __restrict__ dst) {
    int e = blockIdx.y;
    int i = blockIdx.x * blockDim.x + threadIdx.x;
    if (i < EE) atomicAdd(&g_cnt[e * NN + dst[(size_t)e * EE + i]], 1);
}
__global__ void scan_a_kernel() {
    __shared__ int wsum[32];
    int t = threadIdx.x, lane = t & 31, wid = t >> 5;
    int gid = blockIdx.x * 1024 + t;
    int v = (gid < NET * NN) ? g_cnt[gid] : 0;
    int x = v;
#pragma unroll
    for (int o = 1; o < 32; o <<= 1) { int y = __shfl_up_sync(0xffffffffu, x, o); if (lane >= o) x += y; }
    if (lane == 31) wsum[wid] = x;
    __syncthreads();
    if (wid == 0) {
        int s = wsum[lane];
#pragma unroll
        for (int o = 1; o < 32; o <<= 1) { int y = __shfl_up_sync(0xffffffffu, s, o); if (lane >= o) s += y; }
        wsum[lane] = s;
    }
    __syncthreads();
    int pfx = wid ? wsum[wid - 1] : 0;
    if (gid < NET * NN) g_off[gid] = pfx + x - v;
    if (t == 1023) g_bsum[blockIdx.x] = pfx + x;
}
__global__ void scan_b_kernel() {
    __shared__ int wsum[8];
    int t = threadIdx.x, lane = t & 31, wid = t >> 5;
    int v = (t < 196) ? g_bsum[t] : 0;
    int x = v;
#pragma unroll
    for (int o = 1; o < 32; o <<= 1) { int y = __shfl_up_sync(0xffffffffu, x, o); if (lane >= o) x += y; }
    if (lane == 31) wsum[wid] = x;
    __syncthreads();
    if (t == 0) {
        int run = 0;
#pragma unroll
        for (int i = 0; i < 8; i++) { int tmp = wsum[i]; wsum[i] = run; run += tmp; }
    }
    __syncthreads();
    if (t < 196) g_bsum[t] = wsum[wid] + x - v;
}
__global__ void scan_c_kernel() {
    int gid = blockIdx.x * 1024 + threadIdx.x;
    if (gid < NET * NN) {
        int o = g_off[gid] + g_bsum[gid >> 10];
        g_off[gid] = o;
        g_cur[gid] = o;
    }
    if (gid == 0) g_off[NET * NN] = NET * EE;
}
__global__ void fill_kernel(const int* __restrict__ src, const int* __restrict__ dst) {
    int e = blockIdx.y;
    int i = blockIdx.x * blockDim.x + threadIdx.x;
    if (i < EE) {
        int d = dst[(size_t)e * EE + i];
        int pos = atomicAdd(&g_cur[e * NN + d], 1);
        g_sorted[pos] = src[(size_t)e * EE + i];
    }
}

// ================= fused gather + mean + residual + LayerNorm =================
__global__ void gather_ln_kernel(const float* __restrict__ feat,
                                 const float* __restrict__ ln_g, const float* __restrict__ ln_b,
                                 float* __restrict__ out) {
    int w    = (blockIdx.x * blockDim.x + threadIdx.x) >> 5;
    int lane = threadIdx.x & 31;
    if (w >= NN) return;
    float4 a = make_float4(0.f, 0.f, 0.f, 0.f);
#pragma unroll
    for (int e = 0; e < NET; e++) {
        int beg = g_off[e * NN + w], end = g_off[e * NN + w + 1];
        const float* WhE = g_Wh + (size_t)e * NN * DD;
        float4 tot = make_float4(0.f, 0.f, 0.f, 0.f);
        int i = beg;
        for (; i + 2 <= end; i += 2) {
            int s0 = g_sorted[i], s1 = g_sorted[i + 1];
            float4 v0 = ((const float4*)(WhE + (size_t)s0 * DD))[lane];
            float4 v1 = ((const float4*)(WhE + (size_t)s1 * DD))[lane];
            tot.x += v0.x + v1.x; tot.y += v0.y + v1.y;
            tot.z += v0.z + v1.z; tot.w += v0.w + v1.w;
        }
        if (i < end) {
            int s0 = g_sorted[i];
            float4 v0 = ((const float4*)(WhE + (size_t)s0 * DD))[lane];
            tot.x += v0.x; tot.y += v0.y; tot.z += v0.z; tot.w += v0.w;
        }
        float inv = 1.f / fmaxf((float)(end - beg), 1.f);
        a.x += tot.x * inv; a.y += tot.y * inv;
        a.z += tot.z * inv; a.w += tot.w * inv;
    }
    float4 f = ((const float4*)(feat + (size_t)w * DD))[lane];
    float4 h = make_float4(a.x + f.x, a.y + f.y, a.z + f.z, a.w + f.w);

    float s = h.x + h.y + h.z + h.w;
#pragma unroll
    for (int o = 16; o; o >>= 1) s += __shfl_xor_sync(0xffffffffu, s, o);
    float mu = s * (1.0f / 128.0f);

    float dx = h.x - mu, dy = h.y - mu, dz = h.z - mu, dw = h.w - mu;
    float q = dx * dx + dy * dy + dz * dz + dw * dw;
#pragma unroll
    for (int o = 16; o; o >>= 1) q += __shfl_xor_sync(0xffffffffu, q, o);
    float inv = rsqrtf(q * (1.0f / 128.0f) + LN_EPS);

    float4 gg = ((const float4*)ln_g)[lane];
    float4 bb = ((const float4*)ln_b)[lane];
    float4 o4 = make_float4(dx * inv * gg.x + bb.x, dy * inv * gg.y + bb.y,
                            dz * inv * gg.z + bb.z, dw * inv * gg.w + bb.w);
    ((float4*)out)[(size_t)w * 32 + lane] = o4;
}

extern "C" void kernel_launch(void* const* d_in, const int* in_sizes, int n_in,
                              void* d_out, int out_size) {
    const float* feat = (const float*)d_in[0];
    const int*   src  = (const int*)d_in[1];
    const int*   dst  = (const int*)d_in[2];
    const float* Wt   = (const float*)d_in[3];
    const float* bt   = (const float*)d_in[4];
    const float* Kw   = (const float*)d_in[5];
    const float* Kb   = (const float*)d_in[6];
    const float* Qw   = (const float*)d_in[7];
    const float* Qb   = (const float*)d_in[8];
    const float* Vw   = (const float*)d_in[9];
    const float* Vb   = (const float*)d_in[10];
    const float* ln_g = (const float*)d_in[11];
    const float* ln_b = (const float*)d_in[12];
    float* out = (float*)d_out;

    cudaFuncSetAttribute(transform_kernel, cudaFuncAttributeMaxDynamicSharedMemorySize, SMEM_BYTES);

    // weight pre-split + CSR build (independent of transform)
    wsplit_kernel<<<dim3(256, NET), 256>>>(Wt, Kw, Qw, Vw);
    cnt_zero_kernel<<<196, 1024>>>();
    cnt_kernel<<<dim3(EE / 256, NET), 256>>>(dst);
    scan_a_kernel<<<196, 1024>>>();
    scan_b_kernel<<<1, 256>>>();
    scan_c_kernel<<<196, 1024>>>();
    fill_kernel<<<dim3(EE / 256, NET), 256>>>(src, dst);

    transform_kernel<<<dim3((NN + TM - 1) / TM, NET), 256, SMEM_BYTES>>>(
        feat, bt, Kb, Qb, Vb);

    gather_ln_kernel<<<(NN * 32 + 255) / 256, 256>>>(feat, ln_g, ln_b, out);
}

// round 5
// speedup vs baseline: 3.8331x; 1.1048x over previous
#include <cuda_runtime.h>
#include <cuda_bf16.h>
#include <cstdint>

#define NN   100000
#define DD   128
#define EE   800000
#define NET  2
#define TM   128
#define LN_EPS 1e-5f

#define XS 136      // bf16 row stride (272B -> conflict-free ldmatrix)
#define KS 132      // fp32 row stride for K staging
#define LODELTA 34816   // hi-plane -> lo-plane smem delta (128*136*2)

// ---- smem byte offsets ----
#define OFF_XH 0
#define OFF_W0 69632
#define OFF_W1 139264
#define OFF_SC 208896
#define OFF_BI 217088
#define SMEM_BYTES 219136

// ---- scratch (device globals) ----
__device__ __nv_bfloat16 g_Whb[(size_t)NET * NN * DD];      // bf16 messages
__device__ __nv_bfloat16 g_Wsplit[NET * 4 * 2 * DD * DD];   // [e][mat][hi/lo][128][128]
__device__ int g_cnt[NET * NN];
__device__ int g_off[NET * NN + 1];
__device__ int g_cur[NET * NN];
__device__ int g_bsum[256];
__device__ int g_sorted[NET * EE];

// ---- warp MMA primitives ----
__device__ __forceinline__ void ldmat4(uint32_t* r, uint32_t addr) {
    asm volatile("ldmatrix.sync.aligned.m8n8.x4.shared.b16 {%0,%1,%2,%3}, [%4];"
        : "=r"(r[0]), "=r"(r[1]), "=r"(r[2]), "=r"(r[3]) : "r"(addr));
}
__device__ __forceinline__ void ldmat4t(uint32_t* r, uint32_t addr) {
    asm volatile("ldmatrix.sync.aligned.m8n8.x4.trans.shared.b16 {%0,%1,%2,%3}, [%4];"
        : "=r"(r[0]), "=r"(r[1]), "=r"(r[2]), "=r"(r[3]) : "r"(addr));
}
__device__ __forceinline__ void mma16816(float* c, const uint32_t* a, const uint32_t* b) {
    asm volatile("mma.sync.aligned.m16n8k16.row.col.f32.bf16.bf16.f32 "
        "{%0,%1,%2,%3}, {%4,%5,%6,%7}, {%8,%9}, {%0,%1,%2,%3};"
        : "+f"(c[0]), "+f"(c[1]), "+f"(c[2]), "+f"(c[3])
        : "r"(a[0]), "r"(a[1]), "r"(a[2]), "r"(a[3]), "r"(b[0]), "r"(b[1]));
}
#define CP_COMMIT() asm volatile("cp.async.commit_group;" ::: "memory")
#define CP_WAIT(n)  asm volatile("cp.async.wait_group %0;" :: "n"(n) : "memory")

__device__ __forceinline__ void split2(float a, float b, uint32_t& hi, uint32_t& lo) {
    __nv_bfloat162 h, l;
    h.x = __float2bfloat16(a); h.y = __float2bfloat16(b);
    l.x = __float2bfloat16(a - __bfloat162float(h.x));
    l.y = __float2bfloat16(b - __bfloat162float(h.y));
    hi = *(uint32_t*)&h; lo = *(uint32_t*)&l;
}

// cp.async full weight stage (hi+lo planes, 32KB each)
__device__ __forceinline__ void cpw_full(uint32_t sb, int offW, const __nv_bfloat16* __restrict__ gsrc, int t) {
#pragma unroll
    for (int i = 0; i < 8; i++) {
        int u = i * 256 + t;
        int k = u >> 4, n16 = u & 15;
        uint32_t dh = sb + offW + k * (XS * 2) + n16 * 16;
        const char* gh = (const char*)gsrc + k * 256 + n16 * 16;
        asm volatile("cp.async.cg.shared.global [%0], [%1], 16;" :: "r"(dh), "l"(gh));
        asm volatile("cp.async.cg.shared.global [%0], [%1], 16;" :: "r"(dh + LODELTA), "l"(gh + 32768));
    }
}
// hi plane only (for hi-only K/Q GEMMs)
__device__ __forceinline__ void cpw_hi(uint32_t sb, int offW, const __nv_bfloat16* __restrict__ gsrc, int t) {
#pragma unroll
    for (int i = 0; i < 8; i++) {
        int u = i * 256 + t;
        int k = u >> 4, n16 = u & 15;
        uint32_t dh = sb + offW + k * (XS * 2) + n16 * 16;
        const char* gh = (const char*)gsrc + k * 256 + n16 * 16;
        asm volatile("cp.async.cg.shared.global [%0], [%1], 16;" :: "r"(dh), "l"(gh));
    }
}

// emulated-fp32 GEMM: FULL -> Xh*Wh + Xh*Wl + Xl*Wh; else Xh*Wh only
template<bool FULL>
__device__ __forceinline__ void wgemm(char* smem, float acc[16][4], int offW, int w, int lane) {
    const int r = lane & 7, sel = lane >> 3;
    const int rowoff = (sel & 1) ? 8 : 0;
    const int coloff = (sel & 2) ? 8 : 0;
    const uint32_t sb = (uint32_t)__cvta_generic_to_shared(smem);
    const int arow = 16 * w + r + rowoff;
    const uint32_t axh = sb + OFF_XH + (uint32_t)(arow * XS + coloff) * 2;
#pragma unroll
    for (int kk = 0; kk < 8; kk++) {
        uint32_t Ah[4], Al[4];
        ldmat4(Ah, axh + kk * 32);
        if (FULL) ldmat4(Al, axh + LODELTA + kk * 32);
        const int brow = kk * 16 + r + rowoff;
        const uint32_t bh = sb + offW + (uint32_t)(brow * XS + coloff) * 2;
#pragma unroll
        for (int nt16 = 0; nt16 < 8; nt16++) {
            uint32_t Bh[4], Bl[4];
            ldmat4t(Bh, bh + nt16 * 32);
            if (FULL) ldmat4t(Bl, bh + LODELTA + nt16 * 32);
            mma16816(acc[2 * nt16],     Ah, Bh);
            mma16816(acc[2 * nt16 + 1], Ah, Bh + 2);
            if (FULL) {
                mma16816(acc[2 * nt16],     Ah, Bl);
                mma16816(acc[2 * nt16 + 1], Ah, Bl + 2);
                mma16816(acc[2 * nt16],     Al, Bh);
                mma16816(acc[2 * nt16 + 1], Al, Bh + 2);
            }
        }
    }
}

__device__ __forceinline__ void zacc(float acc[16][4]) {
#pragma unroll
    for (int i = 0; i < 16; i++) { acc[i][0] = acc[i][1] = acc[i][2] = acc[i][3] = 0.f; }
}

// ---- pre-split weights: fp32 -> bf16 hi/lo planes ----
__global__ void wsplit_kernel(const float* __restrict__ Wt, const float* __restrict__ Kw,
                              const float* __restrict__ Qw, const float* __restrict__ Vw) {
    int i = blockIdx.x * 256 + threadIdx.x;
    int mat = i >> 14, j = i & 16383;
    int e = blockIdx.y;
    const float* srcs[4] = {Wt, Kw, Qw, Vw};
    float v = srcs[mat][(size_t)e * 16384 + j];
    __nv_bfloat16 h = __float2bfloat16(v);
    __nv_bfloat16 l = __float2bfloat16(v - __bfloat162float(h));
    size_t b = ((size_t)(e * 4 + mat) * 2) * 16384;
    g_Wsplit[b + j] = h;
    g_Wsplit[b + 16384 + j] = l;
}

// ================= fused transform =================
__global__ void __launch_bounds__(256, 1) transform_kernel(
    const float* __restrict__ feat,
    const float* __restrict__ bt, const float* __restrict__ Kb,
    const float* __restrict__ Qb, const float* __restrict__ Vb)
{
    extern __shared__ char smem[];
    const uint32_t sb = (uint32_t)__cvta_generic_to_shared(smem);
    const int e    = blockIdx.y;
    const int base = blockIdx.x * TM;
    const int t    = threadIdx.x;
    const int w = t >> 5, lane = t & 31;
    const int g = lane >> 2, c = lane & 3;
    const int R0 = 16 * w + g, R1 = R0 + 8;
    float* sKf  = (float*)(smem + OFF_W1);
    float* sScf = (float*)(smem + OFF_SC);
    float* sBI  = (float*)(smem + OFF_BI);
    const __nv_bfloat16* Wb = g_Wsplit + (size_t)e * 4 * 2 * 16384;

    cpw_full(sb, OFF_W0, Wb,             t); CP_COMMIT();   // Wt hi+lo
    cpw_hi  (sb, OFF_W1, Wb + 2 * 16384, t); CP_COMMIT();   // Kw hi only

    if (t < 128) {
        sBI[t]       = bt[e * DD + t];
        sBI[128 + t] = Kb[e * DD + t];
        sBI[256 + t] = Qb[e * DD + t];
        sBI[384 + t] = Vb[e * DD + t];
    }

    // feat -> X (bf16 hi/lo), overlapped with weight cp.async
#pragma unroll
    for (int i = 0; i < 16; i++) {
        int u = i * 256 + t;
        int m = u >> 5, k = (u & 31) * 4;
        int node = base + m;
        float4 v = make_float4(0.f, 0.f, 0.f, 0.f);
        if (node < NN) v = *(const float4*)(feat + (size_t)node * DD + k);
        uint32_t h0, l0, h1, l1;
        split2(v.x, v.y, h0, l0);
        split2(v.z, v.w, h1, l1);
        *(uint2*)(smem + OFF_XH + ((size_t)m * XS + k) * 2) = make_uint2(h0, h1);
        *(uint2*)(smem + OFF_XH + LODELTA + ((size_t)m * XS + k) * 2) = make_uint2(l0, l1);
    }
    CP_WAIT(1);
    __syncthreads();

    float acc[16][4];

    // ---- GEMM1: Wh0 = feat @ Wt (full) ----
    zacc(acc);
    wgemm<true>(smem, acc, OFF_W0, w, lane);
    __syncthreads();

    // Wh0 + bt -> X
#pragma unroll
    for (int nt = 0; nt < 16; nt++) {
        int col = nt * 8 + 2 * c;
        float bx = sBI[col], by = sBI[col + 1];
        uint32_t h, l;
        split2(acc[nt][0] + bx, acc[nt][1] + by, h, l);
        *(uint32_t*)(smem + OFF_XH + ((size_t)R0 * XS + col) * 2) = h;
        *(uint32_t*)(smem + OFF_XH + LODELTA + ((size_t)R0 * XS + col) * 2) = l;
        split2(acc[nt][2] + bx, acc[nt][3] + by, h, l);
        *(uint32_t*)(smem + OFF_XH + ((size_t)R1 * XS + col) * 2) = h;
        *(uint32_t*)(smem + OFF_XH + LODELTA + ((size_t)R1 * XS + col) * 2) = l;
    }
    cpw_hi(sb, OFF_W0, Wb + 4 * 16384, t); CP_COMMIT();   // Qw hi (into W0 hi plane)
    CP_WAIT(1);                                           // Kw ready
    __syncthreads();

    // ---- GEMM2: K (hi-only) ----
    zacc(acc);
    wgemm<false>(smem, acc, OFF_W1, w, lane);
    __syncthreads();

    // stage K (+Kb) into W1 region
#pragma unroll
    for (int nt = 0; nt < 16; nt++) {
        int col = nt * 8 + 2 * c;
        float bx = sBI[128 + col], by = sBI[128 + col + 1];
        *(float2*)(sKf + (size_t)R0 * KS + col) = make_float2(acc[nt][0] + bx, acc[nt][1] + by);
        *(float2*)(sKf + (size_t)R1 * KS + col) = make_float2(acc[nt][2] + bx, acc[nt][3] + by);
    }
    CP_WAIT(0);                                           // Qw ready
    __syncthreads();

    // ---- GEMM3: Q (hi-only) ----
    zacc(acc);
    wgemm<false>(smem, acc, OFF_W0, w, lane);
#pragma unroll
    for (int nt = 0; nt < 16; nt++) {
        int col = nt * 8 + 2 * c;
        float bx = sBI[256 + col], by = sBI[256 + col + 1];
        acc[nt][0] += bx; acc[nt][1] += by;
        acc[nt][2] += bx; acc[nt][3] += by;
    }

    // ---- scores ----
    const float scale = 0.17677669529663687f;
#pragma unroll
    for (int gp = 0; gp < 4; gp++) {
        float2 kv0[4], kv1[4];
#pragma unroll
        for (int j = 0; j < 4; j++) {
            kv0[j] = *(float2*)(sKf + (size_t)R0 * KS + gp * 32 + j * 8 + 2 * c);
            kv1[j] = *(float2*)(sKf + (size_t)R1 * KS + gp * 32 + j * 8 + 2 * c);
        }
#pragma unroll
        for (int h = 0; h < 4; h++) {
            float p0 = 0.f, p1 = 0.f;
#pragma unroll
            for (int j = 0; j < 4; j++) {
                p0 += acc[4 * h + j][0] * kv0[j].x + acc[4 * h + j][1] * kv0[j].y;
                p1 += acc[4 * h + j][2] * kv1[j].x + acc[4 * h + j][3] * kv1[j].y;
            }
            p0 += __shfl_xor_sync(0xffffffffu, p0, 1);
            p0 += __shfl_xor_sync(0xffffffffu, p0, 2);
            p1 += __shfl_xor_sync(0xffffffffu, p1, 1);
            p1 += __shfl_xor_sync(0xffffffffu, p1, 2);
            if (c == 0) {
                sScf[R0 * 16 + h * 4 + gp] = p0 * scale;
                sScf[R1 * 16 + h * 4 + gp] = p1 * scale;
            }
        }
    }
    __syncthreads();                                      // K reads done, scores visible

    cpw_full(sb, OFF_W1, Wb + 6 * 16384, t); CP_COMMIT(); // Vw hi+lo (overlaps softmax)

    // ---- softmax ----
#pragma unroll
    for (int i = 0; i < 2; i++) {
        int p = t * 2 + i;
        int row = p >> 2, h = p & 3;
        float4 s = *(float4*)(sScf + row * 16 + h * 4);
        float m = fmaxf(fmaxf(s.x, s.y), fmaxf(s.z, s.w));
        float e0 = __expf(s.x - m), e1 = __expf(s.y - m), e2 = __expf(s.z - m), e3 = __expf(s.w - m);
        float inv = 1.f / (e0 + e1 + e2 + e3);
        *(float4*)(sScf + row * 16 + h * 4) = make_float4(e0 * inv, e1 * inv, e2 * inv, e3 * inv);
    }
    CP_WAIT(0);
    __syncthreads();

    // ---- GEMM4: V (full) ----
    zacc(acc);
    wgemm<true>(smem, acc, OFF_W1, w, lane);
#pragma unroll
    for (int nt = 0; nt < 16; nt++) {
        int col = nt * 8 + 2 * c;
        float bx = sBI[384 + col], by = sBI[384 + col + 1];
        acc[nt][0] += bx; acc[nt][1] += by;
        acc[nt][2] += bx; acc[nt][3] += by;
    }

    // ---- combine -> g_Whb (bf16), low register pressure ----
    const int n0 = base + R0, n1 = base + R1;
    __nv_bfloat16* op0 = g_Whb + ((size_t)e * NN + n0) * DD;
    __nv_bfloat16* op1 = g_Whb + ((size_t)e * NN + n1) * DD;
#pragma unroll
    for (int h = 0; h < 4; h++) {
        float4 a0 = *(float4*)(sScf + R0 * 16 + 4 * h);
        float4 a1 = *(float4*)(sScf + R1 * 16 + 4 * h);
#pragma unroll
        for (int j3 = 0; j3 < 4; j3++) {
            int col = (h * 4 + j3) * 8 + 2 * c;
            float o00 = a0.x * acc[j3][0]      + a0.y * acc[4 + j3][0]
                      + a0.z * acc[8 + j3][0]  + a0.w * acc[12 + j3][0];
            float o01 = a0.x * acc[j3][1]      + a0.y * acc[4 + j3][1]
                      + a0.z * acc[8 + j3][1]  + a0.w * acc[12 + j3][1];
            float o10 = a1.x * acc[j3][2]      + a1.y * acc[4 + j3][2]
                      + a1.z * acc[8 + j3][2]  + a1.w * acc[12 + j3][2];
            float o11 = a1.x * acc[j3][3]      + a1.y * acc[4 + j3][3]
                      + a1.z * acc[8 + j3][3]  + a1.w * acc[12 + j3][3];
            if (n0 < NN) {
                __nv_bfloat162 pk = __floats2bfloat162_rn(o00, o01);
                *(uint32_t*)(op0 + col) = *(uint32_t*)&pk;
            }
            if (n1 < NN) {
                __nv_bfloat162 pk = __floats2bfloat162_rn(o10, o11);
                *(uint32_t*)(op1 + col) = *(uint32_t*)&pk;
            }
        }
    }
}

// ================= CSR build =================
__global__ void cnt_zero_kernel() {
    int i = blockIdx.x * 1024 + threadIdx.x;
    if (i < NET * NN) g_cnt[i] = 0;
}
__global__ void cnt_kernel(const int* __restrict__ dst) {
    int e = blockIdx.y;
    int i = blockIdx.x * blockDim.x + threadIdx.x;
    if (i < EE) atomicAdd(&g_cnt[e * NN + dst[(size_t)e * EE + i]], 1);
}
__global__ void scan_a_kernel() {
    __shared__ int wsum[32];
    int t = threadIdx.x, lane = t & 31, wid = t >> 5;
    int gid = blockIdx.x * 1024 + t;
    int v = (gid < NET * NN) ? g_cnt[gid] : 0;
    int x = v;
#pragma unroll
    for (int o = 1; o < 32; o <<= 1) { int y = __shfl_up_sync(0xffffffffu, x, o); if (lane >= o) x += y; }
    if (lane == 31) wsum[wid] = x;
    __syncthreads();
    if (wid == 0) {
        int s = wsum[lane];
#pragma unroll
        for (int o = 1; o < 32; o <<= 1) { int y = __shfl_up_sync(0xffffffffu, s, o); if (lane >= o) s += y; }
        wsum[lane] = s;
    }
    __syncthreads();
    int pfx = wid ? wsum[wid - 1] : 0;
    if (gid < NET * NN) g_off[gid] = pfx + x - v;
    if (t == 1023) g_bsum[blockIdx.x] = pfx + x;
}
__global__ void scan_b_kernel() {
    __shared__ int wsum[8];
    int t = threadIdx.x, lane = t & 31, wid = t >> 5;
    int v = (t < 196) ? g_bsum[t] : 0;
    int x = v;
#pragma unroll
    for (int o = 1; o < 32; o <<= 1) { int y = __shfl_up_sync(0xffffffffu, x, o); if (lane >= o) x += y; }
    if (lane == 31) wsum[wid] = x;
    __syncthreads();
    if (t == 0) {
        int run = 0;
#pragma unroll
        for (int i = 0; i < 8; i++) { int tmp = wsum[i]; wsum[i] = run; run += tmp; }
    }
    __syncthreads();
    if (t < 196) g_bsum[t] = wsum[wid] + x - v;
}
__global__ void scan_c_kernel() {
    int gid = blockIdx.x * 1024 + threadIdx.x;
    if (gid < NET * NN) {
        int o = g_off[gid] + g_bsum[gid >> 10];
        g_off[gid] = o;
        g_cur[gid] = o;
    }
    if (gid == 0) g_off[NET * NN] = NET * EE;
}
__global__ void fill_kernel(const int* __restrict__ src, const int* __restrict__ dst) {
    int e = blockIdx.y;
    int i = blockIdx.x * blockDim.x + threadIdx.x;
    if (i < EE) {
        int d = dst[(size_t)e * EE + i];
        int pos = atomicAdd(&g_cur[e * NN + d], 1);
        g_sorted[pos] = src[(size_t)e * EE + i];
    }
}

// ================= fused gather (bf16) + mean + residual + LayerNorm =================
__global__ void gather_ln_kernel(const float* __restrict__ feat,
                                 const float* __restrict__ ln_g, const float* __restrict__ ln_b,
                                 float* __restrict__ out) {
    int w    = (blockIdx.x * blockDim.x + threadIdx.x) >> 5;
    int lane = threadIdx.x & 31;
    if (w >= NN) return;
    float a0 = 0.f, a1 = 0.f, a2 = 0.f, a3 = 0.f;
#pragma unroll
    for (int e = 0; e < NET; e++) {
        int beg = g_off[e * NN + w], end = g_off[e * NN + w + 1];
        const __nv_bfloat16* WhE = g_Whb + (size_t)e * NN * DD + lane * 4;
        float t0 = 0.f, t1 = 0.f, t2 = 0.f, t3 = 0.f;
        int i = beg;
        for (; i + 2 <= end; i += 2) {
            int s0 = __ldg(&g_sorted[i]), s1 = __ldg(&g_sorted[i + 1]);
            uint2 u0 = *(const uint2*)(WhE + (size_t)s0 * DD);
            uint2 u1 = *(const uint2*)(WhE + (size_t)s1 * DD);
            float2 p0 = __bfloat1622float2(*(__nv_bfloat162*)&u0.x);
            float2 p1 = __bfloat1622float2(*(__nv_bfloat162*)&u0.y);
            float2 q0 = __bfloat1622float2(*(__nv_bfloat162*)&u1.x);
            float2 q1 = __bfloat1622float2(*(__nv_bfloat162*)&u1.y);
            t0 += p0.x + q0.x; t1 += p0.y + q0.y;
            t2 += p1.x + q1.x; t3 += p1.y + q1.y;
        }
        if (i < end) {
            int s0 = __ldg(&g_sorted[i]);
            uint2 u0 = *(const uint2*)(WhE + (size_t)s0 * DD);
            float2 p0 = __bfloat1622float2(*(__nv_bfloat162*)&u0.x);
            float2 p1 = __bfloat1622float2(*(__nv_bfloat162*)&u0.y);
            t0 += p0.x; t1 += p0.y; t2 += p1.x; t3 += p1.y;
        }
        float inv = 1.f / fmaxf((float)(end - beg), 1.f);
        a0 += t0 * inv; a1 += t1 * inv; a2 += t2 * inv; a3 += t3 * inv;
    }
    float4 f = ((const float4*)(feat + (size_t)w * DD))[lane];
    float4 h = make_float4(a0 + f.x, a1 + f.y, a2 + f.z, a3 + f.w);

    float s = h.x + h.y + h.z + h.w;
#pragma unroll
    for (int o = 16; o; o >>= 1) s += __shfl_xor_sync(0xffffffffu, s, o);
    float mu = s * (1.0f / 128.0f);

    float dx = h.x - mu, dy = h.y - mu, dz = h.z - mu, dw = h.w - mu;
    float q = dx * dx + dy * dy + dz * dz + dw * dw;
#pragma unroll
    for (int o = 16; o; o >>= 1) q += __shfl_xor_sync(0xffffffffu, q, o);
    float inv = rsqrtf(q * (1.0f / 128.0f) + LN_EPS);

    float4 gg = ((const float4*)ln_g)[lane];
    float4 bb = ((const float4*)ln_b)[lane];
    float4 o4 = make_float4(dx * inv * gg.x + bb.x, dy * inv * gg.y + bb.y,
                            dz * inv * gg.z + bb.z, dw * inv * gg.w + bb.w);
    ((float4*)out)[(size_t)w * 32 + lane] = o4;
}

extern "C" void kernel_launch(void* const* d_in, const int* in_sizes, int n_in,
                              void* d_out, int out_size) {
    const float* feat = (const float*)d_in[0];
    const int*   src  = (const int*)d_in[1];
    const int*   dst  = (const int*)d_in[2];
    const float* Wt   = (const float*)d_in[3];
    const float* bt   = (const float*)d_in[4];
    const float* Kw   = (const float*)d_in[5];
    const float* Kb   = (const float*)d_in[6];
    const float* Qw   = (const float*)d_in[7];
    const float* Qb   = (const float*)d_in[8];
    const float* Vw   = (const float*)d_in[9];
    const float* Vb   = (const float*)d_in[10];
    const float* ln_g = (const float*)d_in[11];
    const float* ln_b = (const float*)d_in[12];
    float* out = (float*)d_out;

    cudaFuncSetAttribute(transform_kernel, cudaFuncAttributeMaxDynamicSharedMemorySize, SMEM_BYTES);

    wsplit_kernel<<<dim3(256, NET), 256>>>(Wt, Kw, Qw, Vw);
    cnt_zero_kernel<<<196, 1024>>>();
    cnt_kernel<<<dim3(EE / 256, NET), 256>>>(dst);
    scan_a_kernel<<<196, 1024>>>();
    scan_b_kernel<<<1, 256>>>();
    scan_c_kernel<<<196, 1024>>>();
    fill_kernel<<<dim3(EE / 256, NET), 256>>>(src, dst);

    transform_kernel<<<dim3((NN + TM - 1) / TM, NET), 256, SMEM_BYTES>>>(
        feat, bt, Kb, Qb, Vb);

    gather_ln_kernel<<<(NN * 32 + 255) / 256, 256>>>(feat, ln_g, ln_b, out);
}

// round 8
// speedup vs baseline: 4.6091x; 1.2024x over previous
#include <cuda_runtime.h>
#include <cuda_bf16.h>
#include <cuda_fp16.h>
#include <cstdint>

#define NN   100000
#define DD   128
#define EE   800000
#define NET  2
#define TM   128
#define LN_EPS 1e-5f

#define XS 136          // fp16 row stride (272B -> conflict-free ldmatrix)
#define LODELTA 34816   // XH -> XL plane delta (128*136*2)

// ---- smem byte offsets ----
#define OFF_XH 0
#define OFF_XL 34816        // X lo for GEMM1; then K-stage (fp16) afterwards
#define OFF_W0 69632
#define OFF_W1 104448
#define OFF_SC 139264       // 128*16 fp32 = 8KB
#define OFF_BI 147456       // 512 fp32 = 2KB
#define SMEM_BYTES 149504

// ---- scratch (device globals) ----
__device__ __nv_bfloat16 g_Whb[(size_t)NET * NN * DD];   // bf16 messages
__device__ __half g_Wsplit[NET * 4 * DD * DD];           // fp16 hi-only weights [e][mat][128][128]
__device__ int g_cnt[NET * NN];
__device__ int g_off[NET * NN + 1];
__device__ int g_cur[NET * NN];
__device__ int g_bsum[256];
__device__ int g_sorted[NET * EE];

// ---- warp MMA primitives ----
__device__ __forceinline__ void ldmat4(uint32_t* r, uint32_t addr) {
    asm volatile("ldmatrix.sync.aligned.m8n8.x4.shared.b16 {%0,%1,%2,%3}, [%4];"
        : "=r"(r[0]), "=r"(r[1]), "=r"(r[2]), "=r"(r[3]) : "r"(addr));
}
__device__ __forceinline__ void ldmat4t(uint32_t* r, uint32_t addr) {
    asm volatile("ldmatrix.sync.aligned.m8n8.x4.trans.shared.b16 {%0,%1,%2,%3}, [%4];"
        : "=r"(r[0]), "=r"(r[1]), "=r"(r[2]), "=r"(r[3]) : "r"(addr));
}
__device__ __forceinline__ void mma16816(float* c, const uint32_t* a, const uint32_t* b) {
    asm volatile("mma.sync.aligned.m16n8k16.row.col.f32.f16.f16.f32 "
        "{%0,%1,%2,%3}, {%4,%5,%6,%7}, {%8,%9}, {%0,%1,%2,%3};"
        : "+f"(c[0]), "+f"(c[1]), "+f"(c[2]), "+f"(c[3])
        : "r"(a[0]), "r"(a[1]), "r"(a[2]), "r"(a[3]), "r"(b[0]), "r"(b[1]));
}
#define CP_COMMIT() asm volatile("cp.async.commit_group;" ::: "memory")
#define CP_WAIT(n)  asm volatile("cp.async.wait_group %0;" :: "n"(n) : "memory")

// split two fp32 into fp16x2 hi and fp16x2 lo
__device__ __forceinline__ void split2h(float a, float b, uint32_t& hi, uint32_t& lo) {
    __half ha = __float2half_rn(a), hb = __float2half_rn(b);
    __half la = __float2half_rn(a - __half2float(ha));
    __half lb = __float2half_rn(b - __half2float(hb));
    __half2 h; h.x = ha; h.y = hb;
    __half2 l; l.x = la; l.y = lb;
    hi = *(uint32_t*)&h; lo = *(uint32_t*)&l;
}

// cp.async one 32KB fp16 weight matrix into XS-strided smem
__device__ __forceinline__ void cpw(uint32_t sb, int offW, const __half* __restrict__ gsrc, int t) {
#pragma unroll
    for (int i = 0; i < 8; i++) {
        int u = i * 256 + t;
        int k = u >> 4, n16 = u & 15;
        uint32_t dh = sb + offW + k * (XS * 2) + n16 * 16;
        const char* gh = (const char*)gsrc + k * 256 + n16 * 16;
        asm volatile("cp.async.cg.shared.global [%0], [%1], 16;" :: "r"(dh), "l"(gh));
    }
}

// fp16 GEMM: ALO -> (Xh + Xl)*Wh (2 passes fused); else Xh*Wh
template<bool ALO>
__device__ __forceinline__ void wgemm(char* smem, float acc[16][4], int offW, int w, int lane) {
    const int r = lane & 7, sel = lane >> 3;
    const int rowoff = (sel & 1) ? 8 : 0;
    const int coloff = (sel & 2) ? 8 : 0;
    const uint32_t sb = (uint32_t)__cvta_generic_to_shared(smem);
    const int arow = 16 * w + r + rowoff;
    const uint32_t axh = sb + OFF_XH + (uint32_t)(arow * XS + coloff) * 2;
#pragma unroll
    for (int kk = 0; kk < 8; kk++) {
        uint32_t Ah[4], Al[4];
        ldmat4(Ah, axh + kk * 32);
        if (ALO) ldmat4(Al, axh + LODELTA + kk * 32);
        const int brow = kk * 16 + r + rowoff;
        const uint32_t bh = sb + offW + (uint32_t)(brow * XS + coloff) * 2;
#pragma unroll
        for (int nt16 = 0; nt16 < 8; nt16++) {
            uint32_t Bh[4];
            ldmat4t(Bh, bh + nt16 * 32);
            mma16816(acc[2 * nt16],     Ah, Bh);
            mma16816(acc[2 * nt16 + 1], Ah, Bh + 2);
            if (ALO) {
                mma16816(acc[2 * nt16],     Al, Bh);
                mma16816(acc[2 * nt16 + 1], Al, Bh + 2);
            }
        }
    }
}

__device__ __forceinline__ void zacc(float acc[16][4]) {
#pragma unroll
    for (int i = 0; i < 16; i++) { acc[i][0] = acc[i][1] = acc[i][2] = acc[i][3] = 0.f; }
}

// ---- pre-convert weights: fp32 -> fp16 hi plane ----
__global__ void wsplit_kernel(const float* __restrict__ Wt, const float* __restrict__ Kw,
                              const float* __restrict__ Qw, const float* __restrict__ Vw) {
    int i = blockIdx.x * 256 + threadIdx.x;   // 0..65535
    int mat = i >> 14, j = i & 16383;
    int e = blockIdx.y;
    const float* srcs[4] = {Wt, Kw, Qw, Vw};
    float v = srcs[mat][(size_t)e * 16384 + j];
    g_Wsplit[(size_t)(e * 4 + mat) * 16384 + j] = __float2half_rn(v);
}

// ================= fused transform =================
__global__ void __launch_bounds__(256, 1) transform_kernel(
    const float* __restrict__ feat,
    const float* __restrict__ bt, const float* __restrict__ Kb,
    const float* __restrict__ Qb, const float* __restrict__ Vb)
{
    extern __shared__ char smem[];
    const uint32_t sb = (uint32_t)__cvta_generic_to_shared(smem);
    const int e    = blockIdx.y;
    const int base = blockIdx.x * TM;
    const int t    = threadIdx.x;
    const int w = t >> 5, lane = t & 31;
    const int g = lane >> 2, c = lane & 3;
    const int R0 = 16 * w + g, R1 = R0 + 8;
    float* sScf = (float*)(smem + OFF_SC);
    float* sBI  = (float*)(smem + OFF_BI);
    const __half* Wb = g_Wsplit + (size_t)e * 4 * 16384;

    cpw(sb, OFF_W0, Wb,         t); CP_COMMIT();   // Wt
    cpw(sb, OFF_W1, Wb + 16384, t); CP_COMMIT();   // Kw

    if (t < 128) {
        sBI[t]       = bt[e * DD + t];
        sBI[128 + t] = Kb[e * DD + t];
        sBI[256 + t] = Qb[e * DD + t];
        sBI[384 + t] = Vb[e * DD + t];
    }

    // feat -> X (fp16 hi/lo), overlapped with weight cp.async
#pragma unroll
    for (int i = 0; i < 16; i++) {
        int u = i * 256 + t;
        int m = u >> 5, k = (u & 31) * 4;
        int node = base + m;
        float4 v = make_float4(0.f, 0.f, 0.f, 0.f);
        if (node < NN) v = *(const float4*)(feat + (size_t)node * DD + k);
        uint32_t h0, l0, h1, l1;
        split2h(v.x, v.y, h0, l0);
        split2h(v.z, v.w, h1, l1);
        *(uint2*)(smem + OFF_XH + ((size_t)m * XS + k) * 2) = make_uint2(h0, h1);
        *(uint2*)(smem + OFF_XL + ((size_t)m * XS + k) * 2) = make_uint2(l0, l1);
    }
    CP_WAIT(1);
    __syncthreads();

    float acc[16][4];

    // ---- GEMM1: Wh0 = feat @ Wt ((Xh+Xl)*Wh) ----
    zacc(acc);
    wgemm<true>(smem, acc, OFF_W0, w, lane);
    __syncthreads();

    // Wh0 + bt -> XH (hi only; XL becomes free)
#pragma unroll
    for (int nt = 0; nt < 16; nt++) {
        int col = nt * 8 + 2 * c;
        float bx = sBI[col], by = sBI[col + 1];
        __half2 p0 = __floats2half2_rn(acc[nt][0] + bx, acc[nt][1] + by);
        __half2 p1 = __floats2half2_rn(acc[nt][2] + bx, acc[nt][3] + by);
        *(uint32_t*)(smem + OFF_XH + ((size_t)R0 * XS + col) * 2) = *(uint32_t*)&p0;
        *(uint32_t*)(smem + OFF_XH + ((size_t)R1 * XS + col) * 2) = *(uint32_t*)&p1;
    }
    cpw(sb, OFF_W0, Wb + 2 * 16384, t); CP_COMMIT();   // Qw (W0 free after GEMM1)
    CP_WAIT(1);                                        // Kw ready
    __syncthreads();

    // ---- GEMM2: K (hi-only) ----
    zacc(acc);
    wgemm<false>(smem, acc, OFF_W1, w, lane);
    __syncthreads();                                   // all W1 reads done

    // stage K (+Kb) -> XL as fp16
#pragma unroll
    for (int nt = 0; nt < 16; nt++) {
        int col = nt * 8 + 2 * c;
        float bx = sBI[128 + col], by = sBI[128 + col + 1];
        __half2 p0 = __floats2half2_rn(acc[nt][0] + bx, acc[nt][1] + by);
        __half2 p1 = __floats2half2_rn(acc[nt][2] + bx, acc[nt][3] + by);
        *(uint32_t*)(smem + OFF_XL + ((size_t)R0 * XS + col) * 2) = *(uint32_t*)&p0;
        *(uint32_t*)(smem + OFF_XL + ((size_t)R1 * XS + col) * 2) = *(uint32_t*)&p1;
    }
    CP_WAIT(0);                                        // Qw ready
    __syncthreads();

    cpw(sb, OFF_W1, Wb + 3 * 16384, t); CP_COMMIT();   // Vw (overlaps Q GEMM + scores)

    // ---- GEMM3: Q (hi-only) ----
    zacc(acc);
    wgemm<false>(smem, acc, OFF_W0, w, lane);
#pragma unroll
    for (int nt = 0; nt < 16; nt++) {
        int col = nt * 8 + 2 * c;
        float bx = sBI[256 + col], by = sBI[256 + col + 1];
        acc[nt][0] += bx; acc[nt][1] += by;
        acc[nt][2] += bx; acc[nt][3] += by;
    }

    // ---- scores (K from fp16 XL) ----
    const float scale = 0.17677669529663687f;
#pragma unroll
    for (int gp = 0; gp < 4; gp++) {
        float2 kv0[4], kv1[4];
#pragma unroll
        for (int j = 0; j < 4; j++) {
            __half2 k0 = *(const __half2*)(smem + OFF_XL + ((size_t)R0 * XS + gp * 32 + j * 8 + 2 * c) * 2);
            __half2 k1 = *(const __half2*)(smem + OFF_XL + ((size_t)R1 * XS + gp * 32 + j * 8 + 2 * c) * 2);
            kv0[j] = __half22float2(k0);
            kv1[j] = __half22float2(k1);
        }
#pragma unroll
        for (int h = 0; h < 4; h++) {
            float p0 = 0.f, p1 = 0.f;
#pragma unroll
            for (int j = 0; j < 4; j++) {
                p0 += acc[4 * h + j][0] * kv0[j].x + acc[4 * h + j][1] * kv0[j].y;
                p1 += acc[4 * h + j][2] * kv1[j].x + acc[4 * h + j][3] * kv1[j].y;
            }
            p0 += __shfl_xor_sync(0xffffffffu, p0, 1);
            p0 += __shfl_xor_sync(0xffffffffu, p0, 2);
            p1 += __shfl_xor_sync(0xffffffffu, p1, 1);
            p1 += __shfl_xor_sync(0xffffffffu, p1, 2);
            if (c == 0) {
                sScf[R0 * 16 + h * 4 + gp] = p0 * scale;
                sScf[R1 * 16 + h * 4 + gp] = p1 * scale;
            }
        }
    }
    __syncthreads();

    // ---- softmax ----
#pragma unroll
    for (int i = 0; i < 2; i++) {
        int p = t * 2 + i;
        int row = p >> 2, h = p & 3;
        float4 s = *(float4*)(sScf + row * 16 + h * 4);
        float m = fmaxf(fmaxf(s.x, s.y), fmaxf(s.z, s.w));
        float e0 = __expf(s.x - m), e1 = __expf(s.y - m), e2 = __expf(s.z - m), e3 = __expf(s.w - m);
        float inv = 1.f / (e0 + e1 + e2 + e3);
        *(float4*)(sScf + row * 16 + h * 4) = make_float4(e0 * inv, e1 * inv, e2 * inv, e3 * inv);
    }
    CP_WAIT(0);                                        // Vw ready
    __syncthreads();

    // ---- GEMM4: V (hi-only) ----
    zacc(acc);
    wgemm<false>(smem, acc, OFF_W1, w, lane);
#pragma unroll
    for (int nt = 0; nt < 16; nt++) {
        int col = nt * 8 + 2 * c;
        float bx = sBI[384 + col], by = sBI[384 + col + 1];
        acc[nt][0] += bx; acc[nt][1] += by;
        acc[nt][2] += bx; acc[nt][3] += by;
    }

    // ---- combine -> g_Whb (bf16) ----
    const int n0 = base + R0, n1 = base + R1;
    __nv_bfloat16* op0 = g_Whb + ((size_t)e * NN + n0) * DD;
    __nv_bfloat16* op1 = g_Whb + ((size_t)e * NN + n1) * DD;
#pragma unroll
    for (int h = 0; h < 4; h++) {
        float4 a0 = *(float4*)(sScf + R0 * 16 + 4 * h);
        float4 a1 = *(float4*)(sScf + R1 * 16 + 4 * h);
#pragma unroll
        for (int j3 = 0; j3 < 4; j3++) {
            int col = (h * 4 + j3) * 8 + 2 * c;
            float o00 = a0.x * acc[j3][0]      + a0.y * acc[4 + j3][0]
                      + a0.z * acc[8 + j3][0]  + a0.w * acc[12 + j3][0];
            float o01 = a0.x * acc[j3][1]      + a0.y * acc[4 + j3][1]
                      + a0.z * acc[8 + j3][1]  + a0.w * acc[12 + j3][1];
            float o10 = a1.x * acc[j3][2]      + a1.y * acc[4 + j3][2]
                      + a1.z * acc[8 + j3][2]  + a1.w * acc[12 + j3][2];
            float o11 = a1.x * acc[j3][3]      + a1.y * acc[4 + j3][3]
                      + a1.z * acc[8 + j3][3]  + a1.w * acc[12 + j3][3];
            if (n0 < NN) {
                __nv_bfloat162 pk = __floats2bfloat162_rn(o00, o01);
                *(uint32_t*)(op0 + col) = *(uint32_t*)&pk;
            }
            if (n1 < NN) {
                __nv_bfloat162 pk = __floats2bfloat162_rn(o10, o11);
                *(uint32_t*)(op1 + col) = *(uint32_t*)&pk;
            }
        }
    }
}

// ================= CSR build =================
__global__ void cnt_zero_kernel() {
    int i = blockIdx.x * 1024 + threadIdx.x;
    if (i < NET * NN) g_cnt[i] = 0;
}
__global__ void cnt_kernel(const int* __restrict__ dst) {
    int e = blockIdx.y;
    int i = blockIdx.x * blockDim.x + threadIdx.x;
    if (i < EE) atomicAdd(&g_cnt[e * NN + dst[(size_t)e * EE + i]], 1);
}
__global__ void scan_a_kernel() {
    __shared__ int wsum[32];
    int t = threadIdx.x, lane = t & 31, wid = t >> 5;
    int gid = blockIdx.x * 1024 + t;
    int v = (gid < NET * NN) ? g_cnt[gid] : 0;
    int x = v;
#pragma unroll
    for (int o = 1; o < 32; o <<= 1) { int y = __shfl_up_sync(0xffffffffu, x, o); if (lane >= o) x += y; }
    if (lane == 31) wsum[wid] = x;
    __syncthreads();
    if (wid == 0) {
        int s = wsum[lane];
#pragma unroll
        for (int o = 1; o < 32; o <<= 1) { int y = __shfl_up_sync(0xffffffffu, s, o); if (lane >= o) s += y; }
        wsum[lane] = s;
    }
    __syncthreads();
    int pfx = wid ? wsum[wid - 1] : 0;
    if (gid < NET * NN) g_off[gid] = pfx + x - v;
    if (t == 1023) g_bsum[blockIdx.x] = pfx + x;
}
__global__ void scan_b_kernel() {
    __shared__ int wsum[8];
    int t = threadIdx.x, lane = t & 31, wid = t >> 5;
    int v = (t < 196) ? g_bsum[t] : 0;
    int x = v;
#pragma unroll
    for (int o = 1; o < 32; o <<= 1) { int y = __shfl_up_sync(0xffffffffu, x, o); if (lane >= o) x += y; }
    if (lane == 31) wsum[wid] = x;
    __syncthreads();
    if (t == 0) {
        int run = 0;
#pragma unroll
        for (int i = 0; i < 8; i++) { int tmp = wsum[i]; wsum[i] = run; run += tmp; }
    }
    __syncthreads();
    if (t < 196) g_bsum[t] = wsum[wid] + x - v;
}
__global__ void scan_c_kernel() {
    int gid = blockIdx.x * 1024 + threadIdx.x;
    if (gid < NET * NN) {
        int o = g_off[gid] + g_bsum[gid >> 10];
        g_off[gid] = o;
        g_cur[gid] = o;
    }
    if (gid == 0) g_off[NET * NN] = NET * EE;
}
__global__ void fill_kernel(const int* __restrict__ src, const int* __restrict__ dst) {
    int e = blockIdx.y;
    int i = blockIdx.x * blockDim.x + threadIdx.x;
    if (i < EE) {
        int d = dst[(size_t)e * EE + i];
        int pos = atomicAdd(&g_cur[e * NN + d], 1);
        g_sorted[pos] = src[(size_t)e * EE + i];
    }
}

// ================= fused gather (bf16) + mean + residual + LayerNorm =================
__global__ void gather_ln_kernel(const float* __restrict__ feat,
                                 const float* __restrict__ ln_g, const float* __restrict__ ln_b,
                                 float* __restrict__ out) {
    int w    = (blockIdx.x * blockDim.x + threadIdx.x) >> 5;
    int lane = threadIdx.x & 31;
    if (w >= NN) return;
    float a0 = 0.f, a1 = 0.f, a2 = 0.f, a3 = 0.f;
#pragma unroll
    for (int e = 0; e < NET; e++) {
        int beg = g_off[e * NN + w], end = g_off[e * NN + w + 1];
        const __nv_bfloat16* WhE = g_Whb + (size_t)e * NN * DD + lane * 4;
        float t0 = 0.f, t1 = 0.f, t2 = 0.f, t3 = 0.f;
        int i = beg;
        for (; i + 2 <= end; i += 2) {
            int s0 = __ldg(&g_sorted[i]), s1 = __ldg(&g_sorted[i + 1]);
            uint2 u0 = *(const uint2*)(WhE + (size_t)s0 * DD);
            uint2 u1 = *(const uint2*)(WhE + (size_t)s1 * DD);
            float2 p0 = __bfloat1622float2(*(__nv_bfloat162*)&u0.x);
            float2 p1 = __bfloat1622float2(*(__nv_bfloat162*)&u0.y);
            float2 q0 = __bfloat1622float2(*(__nv_bfloat162*)&u1.x);
            float2 q1 = __bfloat1622float2(*(__nv_bfloat162*)&u1.y);
            t0 += p0.x + q0.x; t1 += p0.y + q0.y;
            t2 += p1.x + q1.x; t3 += p1.y + q1.y;
        }
        if (i < end) {
            int s0 = __ldg(&g_sorted[i]);
            uint2 u0 = *(const uint2*)(WhE + (size_t)s0 * DD);
            float2 p0 = __bfloat1622float2(*(__nv_bfloat162*)&u0.x);
            float2 p1 = __bfloat1622float2(*(__nv_bfloat162*)&u0.y);
            t0 += p0.x; t1 += p0.y; t2 += p1.x; t3 += p1.y;
        }
        float inv = 1.f / fmaxf((float)(end - beg), 1.f);
        a0 += t0 * inv; a1 += t1 * inv; a2 += t2 * inv; a3 += t3 * inv;
    }
    float4 f = ((const float4*)(feat + (size_t)w * DD))[lane];
    float4 h = make_float4(a0 + f.x, a1 + f.y, a2 + f.z, a3 + f.w);

    float s = h.x + h.y + h.z + h.w;
#pragma unroll
    for (int o = 16; o; o >>= 1) s += __shfl_xor_sync(0xffffffffu, s, o);
    float mu = s * (1.0f / 128.0f);

    float dx = h.x - mu, dy = h.y - mu, dz = h.z - mu, dw = h.w - mu;
    float q = dx * dx + dy * dy + dz * dz + dw * dw;
#pragma unroll
    for (int o = 16; o; o >>= 1) q += __shfl_xor_sync(0xffffffffu, q, o);
    float inv = rsqrtf(q * (1.0f / 128.0f) + LN_EPS);

    float4 gg = ((const float4*)ln_g)[lane];
    float4 bb = ((const float4*)ln_b)[lane];
    float4 o4 = make_float4(dx * inv * gg.x + bb.x, dy * inv * gg.y + bb.y,
                            dz * inv * gg.z + bb.z, dw * inv * gg.w + bb.w);
    ((float4*)out)[(size_t)w * 32 + lane] = o4;
}

extern "C" void kernel_launch(void* const* d_in, const int* in_sizes, int n_in,
                              void* d_out, int out_size) {
    const float* feat = (const float*)d_in[0];
    const int*   src  = (const int*)d_in[1];
    const int*   dst  = (const int*)d_in[2];
    const float* Wt   = (const float*)d_in[3];
    const float* bt   = (const float*)d_in[4];
    const float* Kw   = (const float*)d_in[5];
    const float* Kb   = (const float*)d_in[6];
    const float* Qw   = (const float*)d_in[7];
    const float* Qb   = (const float*)d_in[8];
    const float* Vw   = (const float*)d_in[9];
    const float* Vb   = (const float*)d_in[10];
    const float* ln_g = (const float*)d_in[11];
    const float* ln_b = (const float*)d_in[12];
    float* out = (float*)d_out;

    cudaFuncSetAttribute(transform_kernel, cudaFuncAttributeMaxDynamicSharedMemorySize, SMEM_BYTES);

    wsplit_kernel<<<dim3(256, NET), 256>>>(Wt, Kw, Qw, Vw);
    cnt_zero_kernel<<<196, 1024>>>();
    cnt_kernel<<<dim3(EE / 256, NET), 256>>>(dst);
    scan_a_kernel<<<196, 1024>>>();
    scan_b_kernel<<<1, 256>>>();
    scan_c_kernel<<<196, 1024>>>();
    fill_kernel<<<dim3(EE / 256, NET), 256>>>(src, dst);

    transform_kernel<<<dim3((NN + TM - 1) / TM, NET), 256, SMEM_BYTES>>>(
        feat, bt, Kb, Qb, Vb);

    gather_ln_kernel<<<(NN * 32 + 255) / 256, 256>>>(feat, ln_g, ln_b, out);
}